// round 14
// baseline (speedup 1.0000x reference)
#include <cuda_runtime.h>
#include <cuda_bf16.h>
#include <math.h>

#define N_NODES 50000
#define N_EDGES 600000
#define HEADS 8
#define HID 128
#define NCLS 64
#define SCAN_B 256
#define SCAN_G ((N_NODES + SCAN_B - 1) / SCAN_B)

typedef unsigned long long ull;
typedef unsigned short u16;
typedef unsigned int u32;

// ---------------- scratch ----------------
__device__ float g_h0[(size_t)N_NODES * HID];
__device__ float g_as[N_NODES * HEADS];
__device__ float g_ad[N_NODES * HEADS];
__device__ float g_agg0[(size_t)N_NODES * HID];
__device__ float g_avs[HID * HEADS];
__device__ float g_avd[HID * HEADS];
__device__ float g_zout[(size_t)N_NODES * NCLS];
__device__ float g_zout2[(size_t)N_NODES * NCLS];
__device__ u16 g_w0thi[128 * 256];
__device__ u16 g_w0tlo[128 * 256];
__device__ u16 g_w1thi[64 * 1024];
__device__ u16 g_w1tlo[64 * 1024];
__device__ u16 g_zhi[(size_t)N_NODES * 1024];
__device__ u16 g_zlo[(size_t)N_NODES * 1024];
__device__ int g_deg[N_NODES];
__device__ int g_cur[N_NODES];
__device__ int g_rowptr[N_NODES + 1];
__device__ int g_csr_src[N_EDGES];
__device__ int g_bsum[SCAN_G];
__device__ int g_boff[SCAN_G];
__device__ int g_is64;

// ================= warp MMA helpers =================
__device__ __forceinline__ u32 smem_u32(const void* p) {
    u32 a;
    asm("{ .reg .u64 t; cvta.to.shared.u64 t, %1; cvt.u32.u64 %0, t; }" : "=r"(a) : "l"(p));
    return a;
}
__device__ __forceinline__ void ldsm_x4(u32* r, u32 addr) {
    asm volatile("ldmatrix.sync.aligned.m8n8.x4.shared.b16 {%0,%1,%2,%3}, [%4];"
        : "=r"(r[0]), "=r"(r[1]), "=r"(r[2]), "=r"(r[3]) : "r"(addr));
}
__device__ __forceinline__ void mma_bf16(float* c, u32 a0, u32 a1, u32 a2, u32 a3,
                                         u32 b0, u32 b1) {
    asm volatile("mma.sync.aligned.m16n8k16.row.col.f32.bf16.bf16.f32 "
        "{%0,%1,%2,%3}, {%4,%5,%6,%7}, {%8,%9}, {%0,%1,%2,%3};"
        : "+f"(c[0]), "+f"(c[1]), "+f"(c[2]), "+f"(c[3])
        : "r"(a0), "r"(a1), "r"(a2), "r"(a3), "r"(b0), "r"(b1));
}

// ================= f32x2 helpers =================
__device__ __forceinline__ ull pk2(float lo, float hi) {
    ull r; asm("mov.b64 %0, {%1, %2};" : "=l"(r) : "f"(lo), "f"(hi)); return r;
}
__device__ __forceinline__ ull ffma2(ull a, ull b, ull c) {
    ull d; asm("fma.rn.f32x2 %0, %1, %2, %3;" : "=l"(d) : "l"(a), "l"(b), "l"(c)); return d;
}
__device__ __forceinline__ float2 upk2(ull p) {
    float2 v; asm("mov.b64 {%0, %1}, %2;" : "=f"(v.x), "=f"(v.y) : "l"(p)); return v;
}

// ================= bf16 split =================
__device__ __forceinline__ void bsplit(float f, u16* hi, u16* lo) {
    __nv_bfloat16 h = __float2bfloat16(f);
    float r = f - __bfloat162float(h);
    __nv_bfloat16 l = __float2bfloat16(r);
    *hi = *(u16*)&h;
    *lo = *(u16*)&l;
}

// ---------------- init + dtype probe ----------------
__global__ void init_kernel(int* __restrict__ a, int* __restrict__ b,
                            const int* __restrict__ ei_raw) {
    int i = blockIdx.x * blockDim.x + threadIdx.x;
    if (i < N_NODES) { a[i] = 0; b[i] = 0; }
    if (i == 0) {
        int allz = 1;
#pragma unroll
        for (int j = 1; j < 64; j += 2)
            if (ei_raw[j] != 0) { allz = 0; break; }
        g_is64 = allz;
    }
}
__device__ __forceinline__ int edge_src(const void* ei, int e) {
    if (g_is64) return (int)((const long long*)ei)[e];
    return ((const int*)ei)[e];
}
__device__ __forceinline__ int edge_dst(const void* ei, int e) {
    if (g_is64) return (int)((const long long*)ei)[N_EDGES + e];
    return ((const int*)ei)[N_EDGES + e];
}

// ---------------- CSR build ----------------
__global__ void hist_kernel(const void* __restrict__ ei, int* __restrict__ deg) {
    int e = blockIdx.x * blockDim.x + threadIdx.x;
    if (e >= N_EDGES) return;
    atomicAdd(&deg[edge_dst(ei, e)], 1);
}
__global__ void scanA_kernel(const int* __restrict__ deg, int* __restrict__ bsum) {
    __shared__ int ws[8];
    int tid = threadIdx.x, lane = tid & 31, wid = tid >> 5;
    int i = blockIdx.x * SCAN_B + tid;
    int x = (i < N_NODES) ? deg[i] : 0;
#pragma unroll
    for (int o = 16; o; o >>= 1) x += __shfl_down_sync(0xffffffffu, x, o);
    if (lane == 0) ws[wid] = x;
    __syncthreads();
    if (tid == 0) {
        int t = 0;
#pragma unroll
        for (int j = 0; j < 8; j++) t += ws[j];
        bsum[blockIdx.x] = t;
    }
}
__global__ void scanB_kernel(const int* __restrict__ bsum, int* __restrict__ boff) {
    __shared__ int ws[8];
    int tid = threadIdx.x, lane = tid & 31, wid = tid >> 5;
    int v = (tid < SCAN_G) ? bsum[tid] : 0;
    int x = v;
#pragma unroll
    for (int o = 1; o < 32; o <<= 1) {
        int t = __shfl_up_sync(0xffffffffu, x, o);
        if (lane >= o) x += t;
    }
    if (lane == 31) ws[wid] = x;
    __syncthreads();
    if (tid == 0) {
        int run = 0;
#pragma unroll
        for (int j = 0; j < 8; j++) { int t = ws[j]; ws[j] = run; run += t; }
    }
    __syncthreads();
    if (tid < SCAN_G) boff[tid] = x - v + ws[wid];
}
__global__ void scanC_kernel(const int* __restrict__ deg, const int* __restrict__ boff,
                             int* __restrict__ row_ptr) {
    __shared__ int ws[8];
    int tid = threadIdx.x, lane = tid & 31, wid = tid >> 5;
    int i = blockIdx.x * SCAN_B + tid;
    int v = (i < N_NODES) ? deg[i] : 0;
    int x = v;
#pragma unroll
    for (int o = 1; o < 32; o <<= 1) {
        int t = __shfl_up_sync(0xffffffffu, x, o);
        if (lane >= o) x += t;
    }
    if (lane == 31) ws[wid] = x;
    __syncthreads();
    if (tid == 0) {
        int run = 0;
#pragma unroll
        for (int j = 0; j < 8; j++) { int t = ws[j]; ws[j] = run; run += t; }
    }
    __syncthreads();
    if (i < N_NODES) row_ptr[i] = x - v + ws[wid] + boff[blockIdx.x];
    if (blockIdx.x == 0 && tid == 0) row_ptr[N_NODES] = N_EDGES;
}
__global__ void fill_kernel(const void* __restrict__ ei, const int* __restrict__ row_ptr,
                            int* __restrict__ cur, int* __restrict__ csr_src) {
    int e = blockIdx.x * blockDim.x + threadIdx.x;
    if (e >= N_EDGES) return;
    int dst = edge_dst(ei, e);
    int src = edge_src(ei, e);
    int p = row_ptr[dst] + atomicAdd(&cur[dst], 1);
    csr_src[p] = src;
}

// ---------------- prepW0: transpose+split W0 ----------------
__global__ void prepW0_kernel(const float* __restrict__ W0,
                              u16* __restrict__ whi, u16* __restrict__ wlo) {
    int j = blockIdx.x * blockDim.x + threadIdx.x;
    if (j >= 256 * 128) return;
    int k = j >> 7, n = j & 127;
    bsplit(W0[j], &whi[n * 256 + k], &wlo[n * 256 + k]);
}

// ---------------- prep1: W1t[c][h*128+k] = W1[k][h*64+c], split ----------------
__global__ void prep1_kernel(const float* __restrict__ W1,
                             u16* __restrict__ whi, u16* __restrict__ wlo) {
    int i = blockIdx.x * blockDim.x + threadIdx.x;
    if (i >= 128 * 512) return;
    int k = i >> 9;
    int j = i & 511;
    int hh = j >> 6, c = j & 63;
    int o = c * 1024 + hh * 128 + k;
    bsplit(W1[i], &whi[o], &wlo[o]);
}

// ================= gemm0: fp32 A in-staging split, C[M,128]=A[M,256]@B^T =================
__global__ void __launch_bounds__(256, 2) hgemmx_kernel(
    int M, int N, int K,
    const float* __restrict__ A,
    const u16* __restrict__ Bhi, const u16* __restrict__ Blo,
    float* __restrict__ C) {
    __shared__ u16 Ash[2][128][40];
    __shared__ u16 Bsh[2][64][40];
    int tid = threadIdx.x, lane = tid & 31, wid = tid >> 5;
    int row0 = blockIdx.y * 128;
    int col0 = blockIdx.x * 64;
    int wm = wid & 3;
    int wn = wid >> 2;

    float acc[8][4];
#pragma unroll
    for (int i = 0; i < 8; i++)
#pragma unroll
        for (int j = 0; j < 4; j++) acc[i][j] = 0.f;

    const int arow = wm * 32 + (lane & 15);
    const int aoff = (lane >> 4) << 3;
    const int bn = wn * 32 + (lane & 7) + ((lane >> 4) << 3);
    const int boff = ((lane >> 3) & 1) << 3;

    float4 pfa[2][2];
    uint4 pbh, pbl;

    auto ldg = [&](int k0) {
#pragma unroll
        for (int i = 0; i < 2; i++) {
            int idx = tid + i * 256;
            int r = idx >> 2, q = idx & 3;
            int g = row0 + r;
            if (g < M) {
                const float* base = A + (size_t)g * K + k0 + q * 8;
                pfa[i][0] = *(const float4*)base;
                pfa[i][1] = *(const float4*)(base + 4);
            } else {
                pfa[i][0] = make_float4(0.f, 0.f, 0.f, 0.f);
                pfa[i][1] = make_float4(0.f, 0.f, 0.f, 0.f);
            }
        }
        int r = tid >> 2, q = tid & 3;
        pbh = *(const uint4*)(Bhi + (size_t)(col0 + r) * K + k0 + q * 8);
        pbl = *(const uint4*)(Blo + (size_t)(col0 + r) * K + k0 + q * 8);
    };
    auto sts = [&]() {
#pragma unroll
        for (int i = 0; i < 2; i++) {
            int idx = tid + i * 256;
            int r = idx >> 2, q = idx & 3;
            float f[8] = {pfa[i][0].x, pfa[i][0].y, pfa[i][0].z, pfa[i][0].w,
                          pfa[i][1].x, pfa[i][1].y, pfa[i][1].z, pfa[i][1].w};
            u32 hw[4], lw[4];
#pragma unroll
            for (int j = 0; j < 4; j++) {
                u16 h0, l0, h1, l1;
                bsplit(f[2 * j], &h0, &l0);
                bsplit(f[2 * j + 1], &h1, &l1);
                hw[j] = (u32)h0 | ((u32)h1 << 16);
                lw[j] = (u32)l0 | ((u32)l1 << 16);
            }
            *(uint4*)&Ash[0][r][q * 8] = make_uint4(hw[0], hw[1], hw[2], hw[3]);
            *(uint4*)&Ash[1][r][q * 8] = make_uint4(lw[0], lw[1], lw[2], lw[3]);
        }
        int r = tid >> 2, q = tid & 3;
        *(uint4*)&Bsh[0][r][q * 8] = pbh;
        *(uint4*)&Bsh[1][r][q * 8] = pbl;
    };

    ldg(0); sts(); __syncthreads();
    for (int k0 = 0; k0 < K; k0 += 32) {
        if (k0 + 32 < K) ldg(k0 + 32);
#pragma unroll
        for (int ks = 0; ks < 2; ks++) {
            u32 ah[2][4], al[2][4], bh[2][4], bl[2][4];
            int akk = ks * 16 + aoff;
            int bkk = ks * 16 + boff;
#pragma unroll
            for (int mi = 0; mi < 2; mi++) {
                ldsm_x4(ah[mi], smem_u32(&Ash[0][arow + mi * 16][akk]));
                ldsm_x4(al[mi], smem_u32(&Ash[1][arow + mi * 16][akk]));
            }
#pragma unroll
            for (int ni2 = 0; ni2 < 2; ni2++) {
                ldsm_x4(bh[ni2], smem_u32(&Bsh[0][bn + ni2 * 16][bkk]));
                ldsm_x4(bl[ni2], smem_u32(&Bsh[1][bn + ni2 * 16][bkk]));
            }
#pragma unroll
            for (int mi = 0; mi < 2; mi++) {
#pragma unroll
                for (int ni = 0; ni < 4; ni++) {
                    float* c = acc[mi * 4 + ni];
                    u32 b0h = bh[ni >> 1][(ni & 1) * 2];
                    u32 b1h = bh[ni >> 1][(ni & 1) * 2 + 1];
                    u32 b0l = bl[ni >> 1][(ni & 1) * 2];
                    u32 b1l = bl[ni >> 1][(ni & 1) * 2 + 1];
                    mma_bf16(c, ah[mi][0], ah[mi][1], ah[mi][2], ah[mi][3], b0h, b1h);
                    mma_bf16(c, ah[mi][0], ah[mi][1], ah[mi][2], ah[mi][3], b0l, b1l);
                    mma_bf16(c, al[mi][0], al[mi][1], al[mi][2], al[mi][3], b0h, b1h);
                }
            }
        }
        if (k0 + 32 < K) { __syncthreads(); sts(); __syncthreads(); }
    }

    int gid = lane >> 2, tig = lane & 3;
#pragma unroll
    for (int mi = 0; mi < 2; mi++) {
#pragma unroll
        for (int ni = 0; ni < 4; ni++) {
            float* c = acc[mi * 4 + ni];
            int r = row0 + wm * 32 + mi * 16 + gid;
            int col = col0 + wn * 32 + ni * 8 + tig * 2;
            if (r < M) *(float2*)(C + (size_t)r * N + col) = make_float2(c[0], c[1]);
            if (r + 8 < M) *(float2*)(C + (size_t)(r + 8) * N + col) = make_float2(c[2], c[3]);
        }
    }
}

// ================= gemm1 split-K: two K=512 slices =================
__global__ void __launch_bounds__(256, 2) hgemm1_kernel(
    int M,
    const u16* __restrict__ Ahi, const u16* __restrict__ Alo,
    const u16* __restrict__ Bhi, const u16* __restrict__ Blo,
    float* __restrict__ C0, float* __restrict__ C1) {
    const int LDA = 1024, KS = 512, N = 64;
    __shared__ u16 Ash[2][128][40];
    __shared__ u16 Bsh[2][64][40];
    int tid = threadIdx.x, lane = tid & 31, wid = tid >> 5;
    int row0 = blockIdx.y * 128;
    int kbeg = blockIdx.x * KS;
    float* C = blockIdx.x ? C1 : C0;
    int wm = wid & 3;
    int wn = wid >> 2;

    float acc[8][4];
#pragma unroll
    for (int i = 0; i < 8; i++)
#pragma unroll
        for (int j = 0; j < 4; j++) acc[i][j] = 0.f;

    const int arow = wm * 32 + (lane & 15);
    const int aoff = (lane >> 4) << 3;
    const int bn = wn * 32 + (lane & 7) + ((lane >> 4) << 3);
    const int boff = ((lane >> 3) & 1) << 3;

    uint4 pah[2], pal[2], pbh, pbl;

    auto ldg = [&](int k0) {
#pragma unroll
        for (int i = 0; i < 2; i++) {
            int idx = tid + i * 256;
            int r = idx >> 2, q = idx & 3;
            int g = row0 + r;
            if (g < M) {
                pah[i] = *(const uint4*)(Ahi + (size_t)g * LDA + kbeg + k0 + q * 8);
                pal[i] = *(const uint4*)(Alo + (size_t)g * LDA + kbeg + k0 + q * 8);
            } else {
                pah[i] = make_uint4(0, 0, 0, 0);
                pal[i] = make_uint4(0, 0, 0, 0);
            }
        }
        int r = tid >> 2, q = tid & 3;
        pbh = *(const uint4*)(Bhi + (size_t)r * LDA + kbeg + k0 + q * 8);
        pbl = *(const uint4*)(Blo + (size_t)r * LDA + kbeg + k0 + q * 8);
    };
    auto sts = [&]() {
#pragma unroll
        for (int i = 0; i < 2; i++) {
            int idx = tid + i * 256;
            int r = idx >> 2, q = idx & 3;
            *(uint4*)&Ash[0][r][q * 8] = pah[i];
            *(uint4*)&Ash[1][r][q * 8] = pal[i];
        }
        int r = tid >> 2, q = tid & 3;
        *(uint4*)&Bsh[0][r][q * 8] = pbh;
        *(uint4*)&Bsh[1][r][q * 8] = pbl;
    };

    ldg(0); sts(); __syncthreads();
    for (int k0 = 0; k0 < KS; k0 += 32) {
        if (k0 + 32 < KS) ldg(k0 + 32);
#pragma unroll
        for (int ks = 0; ks < 2; ks++) {
            u32 ah[2][4], al[2][4], bh[2][4], bl[2][4];
            int akk = ks * 16 + aoff;
            int bkk = ks * 16 + boff;
#pragma unroll
            for (int mi = 0; mi < 2; mi++) {
                ldsm_x4(ah[mi], smem_u32(&Ash[0][arow + mi * 16][akk]));
                ldsm_x4(al[mi], smem_u32(&Ash[1][arow + mi * 16][akk]));
            }
#pragma unroll
            for (int ni2 = 0; ni2 < 2; ni2++) {
                ldsm_x4(bh[ni2], smem_u32(&Bsh[0][bn + ni2 * 16][bkk]));
                ldsm_x4(bl[ni2], smem_u32(&Bsh[1][bn + ni2 * 16][bkk]));
            }
#pragma unroll
            for (int mi = 0; mi < 2; mi++) {
#pragma unroll
                for (int ni = 0; ni < 4; ni++) {
                    float* c = acc[mi * 4 + ni];
                    u32 b0h = bh[ni >> 1][(ni & 1) * 2];
                    u32 b1h = bh[ni >> 1][(ni & 1) * 2 + 1];
                    u32 b0l = bl[ni >> 1][(ni & 1) * 2];
                    u32 b1l = bl[ni >> 1][(ni & 1) * 2 + 1];
                    mma_bf16(c, ah[mi][0], ah[mi][1], ah[mi][2], ah[mi][3], b0h, b1h);
                    mma_bf16(c, ah[mi][0], ah[mi][1], ah[mi][2], ah[mi][3], b0l, b1l);
                    mma_bf16(c, al[mi][0], al[mi][1], al[mi][2], al[mi][3], b0h, b1h);
                }
            }
        }
        if (k0 + 32 < KS) { __syncthreads(); sts(); __syncthreads(); }
    }

    int gid = lane >> 2, tig = lane & 3;
#pragma unroll
    for (int mi = 0; mi < 2; mi++) {
#pragma unroll
        for (int ni = 0; ni < 4; ni++) {
            float* c = acc[mi * 4 + ni];
            int r = row0 + wm * 32 + mi * 16 + gid;
            int col = wn * 32 + ni * 8 + tig * 2;
            if (r < M) *(float2*)(C + (size_t)r * N + col) = make_float2(c[0], c[1]);
            if (r + 8 < M) *(float2*)(C + (size_t)(r + 8) * N + col) = make_float2(c[2], c[3]);
        }
    }
}

// ---------------- alpha layer0: warp per node ----------------
__global__ void alpha0_kernel(const float* __restrict__ h,
                              const float* __restrict__ av_s,
                              const float* __restrict__ av_d,
                              float* __restrict__ os, float* __restrict__ od) {
    int t = blockIdx.x * blockDim.x + threadIdx.x;
    int n = t >> 5, l = t & 31;
    if (n >= N_NODES) return;
    float4 hv = *(const float4*)(h + (size_t)n * HID + l * 4);
    int hh = l >> 2;
    float4 sa = *(const float4*)(av_s + hh * 16 + (l & 3) * 4);
    float4 da = *(const float4*)(av_d + hh * 16 + (l & 3) * 4);
    float ss = hv.x * sa.x + hv.y * sa.y + hv.z * sa.z + hv.w * sa.w;
    float sd = hv.x * da.x + hv.y * da.y + hv.z * da.z + hv.w * da.w;
    ss += __shfl_xor_sync(0xffffffffu, ss, 1);
    ss += __shfl_xor_sync(0xffffffffu, ss, 2);
    sd += __shfl_xor_sync(0xffffffffu, sd, 1);
    sd += __shfl_xor_sync(0xffffffffu, sd, 2);
    if ((l & 3) == 0) { os[n * 8 + hh] = ss; od[n * 8 + hh] = sd; }
}

// ---------------- layer0 aggregation: WARP per dst ----------------
__global__ void __launch_bounds__(256) agg0_kernel(
    const int* __restrict__ row_ptr, const int* __restrict__ csr_src,
    const float* __restrict__ as, const float* __restrict__ ad,
    const float* __restrict__ h, const float* __restrict__ b0,
    float* __restrict__ out) {
    __shared__ float s_al[8][32 * 8];
    __shared__ int s_src[8][32];
    int w = threadIdx.x >> 5, lane = threadIdx.x & 31;
    int dst = blockIdx.x * 8 + w;
    if (dst >= N_NODES) return;
    float4 d0 = ((const float4*)(ad + dst * 8))[0];
    float4 d1 = ((const float4*)(ad + dst * 8))[1];
    int s = row_ptr[dst], e = row_ptr[dst + 1];
    int hh = lane >> 2;
    float a0 = 0.f, a1 = 0.f, a2 = 0.f, a3 = 0.f, den = 0.f;
    for (int base = s; base < e; base += 32) {
        int n = min(32, e - base);
        if (lane < n) {
            int src = csr_src[base + lane];
            s_src[w][lane] = src;
            float4 s0 = ((const float4*)(as + src * 8))[0];
            float4 s1 = ((const float4*)(as + src * 8))[1];
            float v[8] = {s0.x + d0.x, s0.y + d0.y, s0.z + d0.z, s0.w + d0.w,
                          s1.x + d1.x, s1.y + d1.y, s1.z + d1.z, s1.w + d1.w};
#pragma unroll
            for (int j = 0; j < 8; j++) {
                float t = v[j];
                t = t > 0.f ? t : 0.2f * t;
                v[j] = __expf(t);
            }
            ((float4*)(s_al[w] + lane * 8))[0] = make_float4(v[0], v[1], v[2], v[3]);
            ((float4*)(s_al[w] + lane * 8))[1] = make_float4(v[4], v[5], v[6], v[7]);
        }
        __syncwarp();
#pragma unroll 4
        for (int i = 0; i < n; i++) {
            float a = s_al[w][i * 8 + hh];
            den += a;
            float4 hv = *(const float4*)(h + (size_t)s_src[w][i] * HID + lane * 4);
            a0 += a * hv.x; a1 += a * hv.y; a2 += a * hv.z; a3 += a * hv.w;
        }
        __syncwarp();
    }
    float r = 1.f / (den + 1e-16f);
    float4 bv = *(const float4*)(b0 + lane * 4);
    float o0 = a0 * r + bv.x, o1 = a1 * r + bv.y, o2 = a2 * r + bv.z, o3 = a3 * r + bv.w;
    o0 = o0 > 0.f ? o0 : expm1f(o0);
    o1 = o1 > 0.f ? o1 : expm1f(o1);
    o2 = o2 > 0.f ? o2 : expm1f(o2);
    o3 = o3 > 0.f ? o3 : expm1f(o3);
    *(float4*)(out + (size_t)dst * HID + lane * 4) = make_float4(o0, o1, o2, o3);
}

// ---------------- fold W1 with attention vectors ----------------
__global__ void gemv_w1a_kernel(const float* __restrict__ W1,
                                const float* __restrict__ a_s,
                                const float* __restrict__ a_d,
                                float* __restrict__ avs, float* __restrict__ avd) {
    int o = blockIdx.x * blockDim.x + threadIdx.x;
    if (o >= HID * HEADS) return;
    int k = o >> 3, hh = o & 7;
    const float* wrow = W1 + (size_t)k * 512 + hh * 64;
    const float* sv = a_s + hh * 64;
    const float* dv = a_d + hh * 64;
    float ss = 0.f, sd = 0.f;
#pragma unroll 16
    for (int c = 0; c < 64; c++) {
        float w = wrow[c];
        ss += w * sv[c];
        sd += w * dv[c];
    }
    avs[k * 8 + hh] = ss;
    avd[k * 8 + hh] = sd;
}

// ---------------- alpha layer1: block(128) per 8 nodes ----------------
__global__ void alpha1_kernel(const float* __restrict__ agg0,
                              const float* __restrict__ avs,
                              const float* __restrict__ avd,
                              float* __restrict__ os, float* __restrict__ od) {
    __shared__ float s_a[8][HID + 1];
    __shared__ float s_t[HID][16];
    int tid = threadIdx.x;
    int n0 = blockIdx.x * 8;
#pragma unroll
    for (int i = tid; i < HID * 8; i += 128) {
        int k = i >> 3, hh = i & 7;
        s_t[k][hh] = avs[i];
        s_t[k][8 + hh] = avd[i];
    }
#pragma unroll
    for (int r = 0; r < 8; r++) {
        int n = n0 + r;
        float v = (n < N_NODES) ? agg0[(size_t)n * HID + tid] : 0.f;
        s_a[r][tid] = v;
    }
    __syncthreads();
    int node = tid >> 4;
    int outp = tid & 15;
    float acc = 0.f;
#pragma unroll 8
    for (int k = 0; k < HID; k++) acc += s_a[node][k] * s_t[k][outp];
    int n = n0 + node;
    if (n < N_NODES) {
        if (outp < 8) os[n * 8 + outp] = acc;
        else od[n * 8 + (outp - 8)] = acc;
    }
}

// ---------------- layer1 aggregation: WARP per dst, f32x2 accumulators ----------------
__global__ void __launch_bounds__(256) aggz_kernel(
    const int* __restrict__ row_ptr, const int* __restrict__ csr_src,
    const float* __restrict__ as, const float* __restrict__ ad,
    const float* __restrict__ agg0,
    u16* __restrict__ zhi, u16* __restrict__ zlo) {
    __shared__ float s_al[8][32 * 8];
    __shared__ int s_src[8][32];
    int w = threadIdx.x >> 5, lane = threadIdx.x & 31;
    int dst = blockIdx.x * 8 + w;
    if (dst >= N_NODES) return;
    float4 d0 = ((const float4*)(ad + dst * 8))[0];
    float4 d1 = ((const float4*)(ad + dst * 8))[1];
    int s = row_ptr[dst], e = row_ptr[dst + 1];
    ull accA[8], accB[8];
    float den[8];
#pragma unroll
    for (int hh = 0; hh < 8; hh++) { accA[hh] = 0ull; accB[hh] = 0ull; den[hh] = 0.f; }
    for (int base = s; base < e; base += 32) {
        int n = min(32, e - base);
        if (lane < n) {
            int src = csr_src[base + lane];
            s_src[w][lane] = src;
            float4 s0 = ((const float4*)(as + src * 8))[0];
            float4 s1 = ((const float4*)(as + src * 8))[1];
            float v[8] = {s0.x + d0.x, s0.y + d0.y, s0.z + d0.z, s0.w + d0.w,
                          s1.x + d1.x, s1.y + d1.y, s1.z + d1.z, s1.w + d1.w};
#pragma unroll
            for (int j = 0; j < 8; j++) {
                float t = v[j];
                t = t > 0.f ? t : 0.2f * t;
                v[j] = __expf(t);
            }
            ((float4*)(s_al[w] + lane * 8))[0] = make_float4(v[0], v[1], v[2], v[3]);
            ((float4*)(s_al[w] + lane * 8))[1] = make_float4(v[4], v[5], v[6], v[7]);
        }
        __syncwarp();
#pragma unroll 2
        for (int i = 0; i < n; i++) {
            float4 hv = *(const float4*)(agg0 + (size_t)s_src[w][i] * HID + lane * 4);
            ull hv01 = pk2(hv.x, hv.y);
            ull hv23 = pk2(hv.z, hv.w);
#pragma unroll
            for (int hh = 0; hh < 8; hh++) {
                float a = s_al[w][i * 8 + hh];
                den[hh] += a;
                ull a2 = pk2(a, a);
                accA[hh] = ffma2(a2, hv01, accA[hh]);
                accB[hh] = ffma2(a2, hv23, accB[hh]);
            }
        }
        __syncwarp();
    }
#pragma unroll
    for (int hh = 0; hh < 8; hh++) {
        float r = 0.125f / (den[hh] + 1e-16f);
        float2 vA = upk2(accA[hh]);
        float2 vB = upk2(accB[hh]);
        u16 h0, l0, h1, l1, h2, l2, h3, l3;
        bsplit(vA.x * r, &h0, &l0);
        bsplit(vA.y * r, &h1, &l1);
        bsplit(vB.x * r, &h2, &l2);
        bsplit(vB.y * r, &h3, &l3);
        size_t o32 = ((size_t)dst * 1024 + hh * 128 + lane * 4) >> 1;
        ((uint2*)zhi)[o32 >> 1] = make_uint2((u32)h0 | ((u32)h1 << 16),
                                             (u32)h2 | ((u32)h3 << 16));
        ((uint2*)zlo)[o32 >> 1] = make_uint2((u32)l0 | ((u32)l1 << 16),
                                             (u32)l2 | ((u32)l3 << 16));
    }
}

// ---------------- finalize: log_softmax(z0+z1 + b1); warp per node ----------------
__global__ void finalize_kernel(const float* __restrict__ z0,
                                const float* __restrict__ z1,
                                const float* __restrict__ b1,
                                float* __restrict__ out) {
    int t = blockIdx.x * blockDim.x + threadIdx.x;
    int n = t >> 5, lane = t & 31;
    if (n >= N_NODES) return;
    float v0 = z0[(size_t)n * NCLS + lane] + z1[(size_t)n * NCLS + lane] + b1[lane];
    float v1 = z0[(size_t)n * NCLS + lane + 32] + z1[(size_t)n * NCLS + lane + 32] + b1[lane + 32];
    float mx = fmaxf(v0, v1);
#pragma unroll
    for (int o = 16; o; o >>= 1) mx = fmaxf(mx, __shfl_xor_sync(0xffffffffu, mx, o));
    float s = expf(v0 - mx) + expf(v1 - mx);
#pragma unroll
    for (int o = 16; o; o >>= 1) s += __shfl_xor_sync(0xffffffffu, s, o);
    float lse = mx + logf(s);
    out[(size_t)n * NCLS + lane] = v0 - lse;
    out[(size_t)n * NCLS + lane + 32] = v1 - lse;
}

// ---------------- launch ----------------
extern "C" void kernel_launch(void* const* d_in, const int* in_sizes, int n_in,
                              void* d_out, int out_size) {
    const float* x   = (const float*)d_in[0];
    const void*  ei  = d_in[1];
    const float* W0  = (const float*)d_in[2];
    const float* as0 = (const float*)d_in[3];
    const float* ad0 = (const float*)d_in[4];
    const float* b0  = (const float*)d_in[5];
    const float* W1  = (const float*)d_in[6];
    const float* as1 = (const float*)d_in[7];
    const float* ad1 = (const float*)d_in[8];
    const float* b1  = (const float*)d_in[9];
    float* out = (float*)d_out;

    float *h0, *as, *ad, *agg0, *avs, *avd, *zout, *zout2;
    u16 *w0thi, *w0tlo, *w1thi, *w1tlo, *zhi, *zlo;
    int *deg, *cur, *rowptr, *csrs, *bsum, *boff;
    cudaGetSymbolAddress((void**)&h0,    g_h0);
    cudaGetSymbolAddress((void**)&as,    g_as);
    cudaGetSymbolAddress((void**)&ad,    g_ad);
    cudaGetSymbolAddress((void**)&agg0,  g_agg0);
    cudaGetSymbolAddress((void**)&avs,   g_avs);
    cudaGetSymbolAddress((void**)&avd,   g_avd);
    cudaGetSymbolAddress((void**)&zout,  g_zout);
    cudaGetSymbolAddress((void**)&zout2, g_zout2);
    cudaGetSymbolAddress((void**)&w0thi, g_w0thi);
    cudaGetSymbolAddress((void**)&w0tlo, g_w0tlo);
    cudaGetSymbolAddress((void**)&w1thi, g_w1thi);
    cudaGetSymbolAddress((void**)&w1tlo, g_w1tlo);
    cudaGetSymbolAddress((void**)&zhi,   g_zhi);
    cudaGetSymbolAddress((void**)&zlo,   g_zlo);
    cudaGetSymbolAddress((void**)&deg,   g_deg);
    cudaGetSymbolAddress((void**)&cur,   g_cur);
    cudaGetSymbolAddress((void**)&rowptr,g_rowptr);
    cudaGetSymbolAddress((void**)&csrs,  g_csr_src);
    cudaGetSymbolAddress((void**)&bsum,  g_bsum);
    cudaGetSymbolAddress((void**)&boff,  g_boff);

    const int TB = 256;
    const int EBLK = (N_EDGES + TB - 1) / TB;
    const int NBLK = (N_NODES + TB - 1) / TB;
    const int WBLK = (N_NODES * 32 + TB - 1) / TB;
    const int MBLK = (N_NODES + 127) / 128;

    // launches 0-2
    init_kernel<<<NBLK, TB>>>(deg, cur, (const int*)ei);
    hist_kernel<<<EBLK, TB>>>(ei, deg);
    prepW0_kernel<<<(256 * 128 + TB - 1) / TB, TB>>>(W0, w0thi, w0tlo);
    // launch 3: gemm0 (profiled)
    hgemmx_kernel<<<dim3(2, MBLK), 256>>>(N_NODES, 128, 256, x, w0thi, w0tlo, h0);

    // CSR completion
    scanA_kernel<<<SCAN_G, SCAN_B>>>(deg, bsum);
    scanB_kernel<<<1, 256>>>(bsum, boff);
    scanC_kernel<<<SCAN_G, SCAN_B>>>(deg, boff, rowptr);
    fill_kernel<<<EBLK, TB>>>(ei, rowptr, cur, csrs);

    // layer 0
    alpha0_kernel<<<WBLK, TB>>>(h0, as0, ad0, as, ad);
    agg0_kernel<<<(N_NODES + 7) / 8, 256>>>(rowptr, csrs, as, ad, h0, b0, agg0);

    // layer 1
    prep1_kernel<<<(128 * 512 + TB - 1) / TB, TB>>>(W1, w1thi, w1tlo);
    gemv_w1a_kernel<<<(HID * HEADS + TB - 1) / TB, TB>>>(W1, as1, ad1, avs, avd);
    alpha1_kernel<<<(N_NODES + 7) / 8, 128>>>(agg0, avs, avd, as, ad);
    aggz_kernel<<<(N_NODES + 7) / 8, 256>>>(rowptr, csrs, as, ad, agg0, zhi, zlo);
    hgemm1_kernel<<<dim3(2, MBLK), 256>>>(N_NODES, zhi, zlo, w1thi, w1tlo, zout, zout2);
    finalize_kernel<<<WBLK, TB>>>(zout, zout2, b1, out);
}

// round 15
// speedup vs baseline: 1.0802x; 1.0802x over previous
#include <cuda_runtime.h>
#include <cuda_bf16.h>
#include <math.h>

#define N_NODES 50000
#define N_EDGES 600000
#define HEADS 8
#define HID 128
#define NCLS 64
#define SCAN_B 256
#define SCAN_G ((N_NODES + SCAN_B - 1) / SCAN_B)

typedef unsigned long long ull;
typedef unsigned short u16;
typedef unsigned int u32;

// ---------------- scratch ----------------
__device__ float g_h0[(size_t)N_NODES * HID];
__device__ float g_as[N_NODES * HEADS];
__device__ float g_ad[N_NODES * HEADS];
__device__ float g_agg0[(size_t)N_NODES * HID];
__device__ float g_avs[HID * HEADS];
__device__ float g_avd[HID * HEADS];
__device__ float g_zout[(size_t)N_NODES * NCLS];
__device__ float g_zout2[(size_t)N_NODES * NCLS];
__device__ u16 g_w0thi[128 * 256];
__device__ u16 g_w0tlo[128 * 256];
__device__ u16 g_w1thi[64 * 1024];
__device__ u16 g_w1tlo[64 * 1024];
__device__ u16 g_zhi[(size_t)N_NODES * 1024];
__device__ u16 g_zlo[(size_t)N_NODES * 1024];
__device__ int g_deg[N_NODES];
__device__ int g_cur[N_NODES];
__device__ int g_rowptr[N_NODES + 1];
__device__ int g_csr_src[N_EDGES];
__device__ int g_bsum[SCAN_G];
__device__ int g_boff[SCAN_G];
__device__ int g_is64;

// ================= warp MMA helpers =================
__device__ __forceinline__ u32 smem_u32(const void* p) {
    u32 a;
    asm("{ .reg .u64 t; cvta.to.shared.u64 t, %1; cvt.u32.u64 %0, t; }" : "=r"(a) : "l"(p));
    return a;
}
__device__ __forceinline__ void ldsm_x4(u32* r, u32 addr) {
    asm volatile("ldmatrix.sync.aligned.m8n8.x4.shared.b16 {%0,%1,%2,%3}, [%4];"
        : "=r"(r[0]), "=r"(r[1]), "=r"(r[2]), "=r"(r[3]) : "r"(addr));
}
__device__ __forceinline__ void mma_bf16(float* c, u32 a0, u32 a1, u32 a2, u32 a3,
                                         u32 b0, u32 b1) {
    asm volatile("mma.sync.aligned.m16n8k16.row.col.f32.bf16.bf16.f32 "
        "{%0,%1,%2,%3}, {%4,%5,%6,%7}, {%8,%9}, {%0,%1,%2,%3};"
        : "+f"(c[0]), "+f"(c[1]), "+f"(c[2]), "+f"(c[3])
        : "r"(a0), "r"(a1), "r"(a2), "r"(a3), "r"(b0), "r"(b1));
}

// ================= bf16 split =================
__device__ __forceinline__ void bsplit(float f, u16* hi, u16* lo) {
    __nv_bfloat16 h = __float2bfloat16(f);
    float r = f - __bfloat162float(h);
    __nv_bfloat16 l = __float2bfloat16(r);
    *hi = *(u16*)&h;
    *lo = *(u16*)&l;
}

// ---------------- init + dtype probe ----------------
__global__ void init_kernel(int* __restrict__ a, int* __restrict__ b,
                            const int* __restrict__ ei_raw) {
    int i = blockIdx.x * blockDim.x + threadIdx.x;
    if (i < N_NODES) { a[i] = 0; b[i] = 0; }
    if (i == 0) {
        int allz = 1;
#pragma unroll
        for (int j = 1; j < 64; j += 2)
            if (ei_raw[j] != 0) { allz = 0; break; }
        g_is64 = allz;
    }
}
__device__ __forceinline__ int edge_src(const void* ei, int e) {
    if (g_is64) return (int)((const long long*)ei)[e];
    return ((const int*)ei)[e];
}
__device__ __forceinline__ int edge_dst(const void* ei, int e) {
    if (g_is64) return (int)((const long long*)ei)[N_EDGES + e];
    return ((const int*)ei)[N_EDGES + e];
}

// ---------------- CSR build ----------------
__global__ void hist_kernel(const void* __restrict__ ei, int* __restrict__ deg) {
    int e = blockIdx.x * blockDim.x + threadIdx.x;
    if (e >= N_EDGES) return;
    atomicAdd(&deg[edge_dst(ei, e)], 1);
}
__global__ void scanA_kernel(const int* __restrict__ deg, int* __restrict__ bsum) {
    __shared__ int ws[8];
    int tid = threadIdx.x, lane = tid & 31, wid = tid >> 5;
    int i = blockIdx.x * SCAN_B + tid;
    int x = (i < N_NODES) ? deg[i] : 0;
#pragma unroll
    for (int o = 16; o; o >>= 1) x += __shfl_down_sync(0xffffffffu, x, o);
    if (lane == 0) ws[wid] = x;
    __syncthreads();
    if (tid == 0) {
        int t = 0;
#pragma unroll
        for (int j = 0; j < 8; j++) t += ws[j];
        bsum[blockIdx.x] = t;
    }
}
__global__ void scanB_kernel(const int* __restrict__ bsum, int* __restrict__ boff) {
    __shared__ int ws[8];
    int tid = threadIdx.x, lane = tid & 31, wid = tid >> 5;
    int v = (tid < SCAN_G) ? bsum[tid] : 0;
    int x = v;
#pragma unroll
    for (int o = 1; o < 32; o <<= 1) {
        int t = __shfl_up_sync(0xffffffffu, x, o);
        if (lane >= o) x += t;
    }
    if (lane == 31) ws[wid] = x;
    __syncthreads();
    if (tid == 0) {
        int run = 0;
#pragma unroll
        for (int j = 0; j < 8; j++) { int t = ws[j]; ws[j] = run; run += t; }
    }
    __syncthreads();
    if (tid < SCAN_G) boff[tid] = x - v + ws[wid];
}
__global__ void scanC_kernel(const int* __restrict__ deg, const int* __restrict__ boff,
                             int* __restrict__ row_ptr) {
    __shared__ int ws[8];
    int tid = threadIdx.x, lane = tid & 31, wid = tid >> 5;
    int i = blockIdx.x * SCAN_B + tid;
    int v = (i < N_NODES) ? deg[i] : 0;
    int x = v;
#pragma unroll
    for (int o = 1; o < 32; o <<= 1) {
        int t = __shfl_up_sync(0xffffffffu, x, o);
        if (lane >= o) x += t;
    }
    if (lane == 31) ws[wid] = x;
    __syncthreads();
    if (tid == 0) {
        int run = 0;
#pragma unroll
        for (int j = 0; j < 8; j++) { int t = ws[j]; ws[j] = run; run += t; }
    }
    __syncthreads();
    if (i < N_NODES) row_ptr[i] = x - v + ws[wid] + boff[blockIdx.x];
    if (blockIdx.x == 0 && tid == 0) row_ptr[N_NODES] = N_EDGES;
}
__global__ void fill_kernel(const void* __restrict__ ei, const int* __restrict__ row_ptr,
                            int* __restrict__ cur, int* __restrict__ csr_src) {
    int e = blockIdx.x * blockDim.x + threadIdx.x;
    if (e >= N_EDGES) return;
    int dst = edge_dst(ei, e);
    int src = edge_src(ei, e);
    int p = row_ptr[dst] + atomicAdd(&cur[dst], 1);
    csr_src[p] = src;
}

// ---------------- prep_all: W0 transpose+split | W1 stack+split | W1·a fold ----------------
__global__ void prep_all_kernel(const float* __restrict__ W0, const float* __restrict__ W1,
                                const float* __restrict__ a_s, const float* __restrict__ a_d,
                                u16* __restrict__ w0thi, u16* __restrict__ w0tlo,
                                u16* __restrict__ w1thi, u16* __restrict__ w1tlo,
                                float* __restrict__ avs, float* __restrict__ avd) {
    int i = blockIdx.x * blockDim.x + threadIdx.x;
    if (i < 256 * 128) {
        int k = i >> 7, n = i & 127;
        bsplit(W0[i], &w0thi[n * 256 + k], &w0tlo[n * 256 + k]);
    } else if (i < 256 * 128 + 128 * 512) {
        int j = i - 256 * 128;
        int k = j >> 9;
        int jj = j & 511;
        int hh = jj >> 6, c = jj & 63;
        int o = c * 1024 + hh * 128 + k;
        bsplit(W1[j], &w1thi[o], &w1tlo[o]);
    } else {
        int o = i - 256 * 128 - 128 * 512;
        if (o < HID * HEADS) {
            int k = o >> 3, hh = o & 7;
            const float* wrow = W1 + (size_t)k * 512 + hh * 64;
            const float* sv = a_s + hh * 64;
            const float* dv = a_d + hh * 64;
            float ss = 0.f, sd = 0.f;
#pragma unroll 16
            for (int c = 0; c < 64; c++) {
                float w = wrow[c];
                ss += w * sv[c];
                sd += w * dv[c];
            }
            avs[k * 8 + hh] = ss;
            avd[k * 8 + hh] = sd;
        }
    }
}

// ================= gemm0: fp32 A in-staging split, C[M,128]=A[M,256]@B^T =================
__global__ void __launch_bounds__(256) hgemmx_kernel(
    int M, int N, int K,
    const float* __restrict__ A,
    const u16* __restrict__ Bhi, const u16* __restrict__ Blo,
    float* __restrict__ C) {
    __shared__ u16 Ash[2][128][40];
    __shared__ u16 Bsh[2][64][40];
    int tid = threadIdx.x, lane = tid & 31, wid = tid >> 5;
    int row0 = blockIdx.y * 128;
    int col0 = blockIdx.x * 64;
    int wm = wid & 3;
    int wn = wid >> 2;

    float acc[8][4];
#pragma unroll
    for (int i = 0; i < 8; i++)
#pragma unroll
        for (int j = 0; j < 4; j++) acc[i][j] = 0.f;

    const int arow = wm * 32 + (lane & 15);
    const int aoff = (lane >> 4) << 3;
    const int bn = wn * 32 + (lane & 7) + ((lane >> 4) << 3);
    const int boff = ((lane >> 3) & 1) << 3;

    float4 pfa[2][2];
    uint4 pbh, pbl;

    auto ldg = [&](int k0) {
#pragma unroll
        for (int i = 0; i < 2; i++) {
            int idx = tid + i * 256;
            int r = idx >> 2, q = idx & 3;
            int g = row0 + r;
            if (g < M) {
                const float* base = A + (size_t)g * K + k0 + q * 8;
                pfa[i][0] = *(const float4*)base;
                pfa[i][1] = *(const float4*)(base + 4);
            } else {
                pfa[i][0] = make_float4(0.f, 0.f, 0.f, 0.f);
                pfa[i][1] = make_float4(0.f, 0.f, 0.f, 0.f);
            }
        }
        int r = tid >> 2, q = tid & 3;
        pbh = *(const uint4*)(Bhi + (size_t)(col0 + r) * K + k0 + q * 8);
        pbl = *(const uint4*)(Blo + (size_t)(col0 + r) * K + k0 + q * 8);
    };
    auto sts = [&]() {
#pragma unroll
        for (int i = 0; i < 2; i++) {
            int idx = tid + i * 256;
            int r = idx >> 2, q = idx & 3;
            float f[8] = {pfa[i][0].x, pfa[i][0].y, pfa[i][0].z, pfa[i][0].w,
                          pfa[i][1].x, pfa[i][1].y, pfa[i][1].z, pfa[i][1].w};
            u32 hw[4], lw[4];
#pragma unroll
            for (int j = 0; j < 4; j++) {
                u16 h0, l0, h1, l1;
                bsplit(f[2 * j], &h0, &l0);
                bsplit(f[2 * j + 1], &h1, &l1);
                hw[j] = (u32)h0 | ((u32)h1 << 16);
                lw[j] = (u32)l0 | ((u32)l1 << 16);
            }
            *(uint4*)&Ash[0][r][q * 8] = make_uint4(hw[0], hw[1], hw[2], hw[3]);
            *(uint4*)&Ash[1][r][q * 8] = make_uint4(lw[0], lw[1], lw[2], lw[3]);
        }
        int r = tid >> 2, q = tid & 3;
        *(uint4*)&Bsh[0][r][q * 8] = pbh;
        *(uint4*)&Bsh[1][r][q * 8] = pbl;
    };

    ldg(0); sts(); __syncthreads();
    for (int k0 = 0; k0 < K; k0 += 32) {
        if (k0 + 32 < K) ldg(k0 + 32);
#pragma unroll
        for (int ks = 0; ks < 2; ks++) {
            u32 ah[2][4], al[2][4], bh[2][4], bl[2][4];
            int akk = ks * 16 + aoff;
            int bkk = ks * 16 + boff;
#pragma unroll
            for (int mi = 0; mi < 2; mi++) {
                ldsm_x4(ah[mi], smem_u32(&Ash[0][arow + mi * 16][akk]));
                ldsm_x4(al[mi], smem_u32(&Ash[1][arow + mi * 16][akk]));
            }
#pragma unroll
            for (int ni2 = 0; ni2 < 2; ni2++) {
                ldsm_x4(bh[ni2], smem_u32(&Bsh[0][bn + ni2 * 16][bkk]));
                ldsm_x4(bl[ni2], smem_u32(&Bsh[1][bn + ni2 * 16][bkk]));
            }
#pragma unroll
            for (int mi = 0; mi < 2; mi++) {
#pragma unroll
                for (int ni = 0; ni < 4; ni++) {
                    float* c = acc[mi * 4 + ni];
                    u32 b0h = bh[ni >> 1][(ni & 1) * 2];
                    u32 b1h = bh[ni >> 1][(ni & 1) * 2 + 1];
                    u32 b0l = bl[ni >> 1][(ni & 1) * 2];
                    u32 b1l = bl[ni >> 1][(ni & 1) * 2 + 1];
                    mma_bf16(c, ah[mi][0], ah[mi][1], ah[mi][2], ah[mi][3], b0h, b1h);
                    mma_bf16(c, ah[mi][0], ah[mi][1], ah[mi][2], ah[mi][3], b0l, b1l);
                    mma_bf16(c, al[mi][0], al[mi][1], al[mi][2], al[mi][3], b0h, b1h);
                }
            }
        }
        if (k0 + 32 < K) { __syncthreads(); sts(); __syncthreads(); }
    }

    int gid = lane >> 2, tig = lane & 3;
#pragma unroll
    for (int mi = 0; mi < 2; mi++) {
#pragma unroll
        for (int ni = 0; ni < 4; ni++) {
            float* c = acc[mi * 4 + ni];
            int r = row0 + wm * 32 + mi * 16 + gid;
            int col = col0 + wn * 32 + ni * 8 + tig * 2;
            if (r < M) *(float2*)(C + (size_t)r * N + col) = make_float2(c[0], c[1]);
            if (r + 8 < M) *(float2*)(C + (size_t)(r + 8) * N + col) = make_float2(c[2], c[3]);
        }
    }
}

// ================= gemm1 split-K: two K=512 slices =================
__global__ void __launch_bounds__(256) hgemm1_kernel(
    int M,
    const u16* __restrict__ Ahi, const u16* __restrict__ Alo,
    const u16* __restrict__ Bhi, const u16* __restrict__ Blo,
    float* __restrict__ C0, float* __restrict__ C1) {
    const int LDA = 1024, KS = 512, N = 64;
    __shared__ u16 Ash[2][128][40];
    __shared__ u16 Bsh[2][64][40];
    int tid = threadIdx.x, lane = tid & 31, wid = tid >> 5;
    int row0 = blockIdx.y * 128;
    int kbeg = blockIdx.x * KS;
    float* C = blockIdx.x ? C1 : C0;
    int wm = wid & 3;
    int wn = wid >> 2;

    float acc[8][4];
#pragma unroll
    for (int i = 0; i < 8; i++)
#pragma unroll
        for (int j = 0; j < 4; j++) acc[i][j] = 0.f;

    const int arow = wm * 32 + (lane & 15);
    const int aoff = (lane >> 4) << 3;
    const int bn = wn * 32 + (lane & 7) + ((lane >> 4) << 3);
    const int boff = ((lane >> 3) & 1) << 3;

    uint4 pah[2], pal[2], pbh, pbl;

    auto ldg = [&](int k0) {
#pragma unroll
        for (int i = 0; i < 2; i++) {
            int idx = tid + i * 256;
            int r = idx >> 2, q = idx & 3;
            int g = row0 + r;
            if (g < M) {
                pah[i] = *(const uint4*)(Ahi + (size_t)g * LDA + kbeg + k0 + q * 8);
                pal[i] = *(const uint4*)(Alo + (size_t)g * LDA + kbeg + k0 + q * 8);
            } else {
                pah[i] = make_uint4(0, 0, 0, 0);
                pal[i] = make_uint4(0, 0, 0, 0);
            }
        }
        int r = tid >> 2, q = tid & 3;
        pbh = *(const uint4*)(Bhi + (size_t)r * LDA + kbeg + k0 + q * 8);
        pbl = *(const uint4*)(Blo + (size_t)r * LDA + kbeg + k0 + q * 8);
    };
    auto sts = [&]() {
#pragma unroll
        for (int i = 0; i < 2; i++) {
            int idx = tid + i * 256;
            int r = idx >> 2, q = idx & 3;
            *(uint4*)&Ash[0][r][q * 8] = pah[i];
            *(uint4*)&Ash[1][r][q * 8] = pal[i];
        }
        int r = tid >> 2, q = tid & 3;
        *(uint4*)&Bsh[0][r][q * 8] = pbh;
        *(uint4*)&Bsh[1][r][q * 8] = pbl;
    };

    ldg(0); sts(); __syncthreads();
    for (int k0 = 0; k0 < KS; k0 += 32) {
        if (k0 + 32 < KS) ldg(k0 + 32);
#pragma unroll
        for (int ks = 0; ks < 2; ks++) {
            u32 ah[2][4], al[2][4], bh[2][4], bl[2][4];
            int akk = ks * 16 + aoff;
            int bkk = ks * 16 + boff;
#pragma unroll
            for (int mi = 0; mi < 2; mi++) {
                ldsm_x4(ah[mi], smem_u32(&Ash[0][arow + mi * 16][akk]));
                ldsm_x4(al[mi], smem_u32(&Ash[1][arow + mi * 16][akk]));
            }
#pragma unroll
            for (int ni2 = 0; ni2 < 2; ni2++) {
                ldsm_x4(bh[ni2], smem_u32(&Bsh[0][bn + ni2 * 16][bkk]));
                ldsm_x4(bl[ni2], smem_u32(&Bsh[1][bn + ni2 * 16][bkk]));
            }
#pragma unroll
            for (int mi = 0; mi < 2; mi++) {
#pragma unroll
                for (int ni = 0; ni < 4; ni++) {
                    float* c = acc[mi * 4 + ni];
                    u32 b0h = bh[ni >> 1][(ni & 1) * 2];
                    u32 b1h = bh[ni >> 1][(ni & 1) * 2 + 1];
                    u32 b0l = bl[ni >> 1][(ni & 1) * 2];
                    u32 b1l = bl[ni >> 1][(ni & 1) * 2 + 1];
                    mma_bf16(c, ah[mi][0], ah[mi][1], ah[mi][2], ah[mi][3], b0h, b1h);
                    mma_bf16(c, ah[mi][0], ah[mi][1], ah[mi][2], ah[mi][3], b0l, b1l);
                    mma_bf16(c, al[mi][0], al[mi][1], al[mi][2], al[mi][3], b0h, b1h);
                }
            }
        }
        if (k0 + 32 < KS) { __syncthreads(); sts(); __syncthreads(); }
    }

    int gid = lane >> 2, tig = lane & 3;
#pragma unroll
    for (int mi = 0; mi < 2; mi++) {
#pragma unroll
        for (int ni = 0; ni < 4; ni++) {
            float* c = acc[mi * 4 + ni];
            int r = row0 + wm * 32 + mi * 16 + gid;
            int col = wn * 32 + ni * 8 + tig * 2;
            if (r < M) *(float2*)(C + (size_t)r * N + col) = make_float2(c[0], c[1]);
            if (r + 8 < M) *(float2*)(C + (size_t)(r + 8) * N + col) = make_float2(c[2], c[3]);
        }
    }
}

// ---------------- alpha layer0: warp per node ----------------
__global__ void alpha0_kernel(const float* __restrict__ h,
                              const float* __restrict__ av_s,
                              const float* __restrict__ av_d,
                              float* __restrict__ os, float* __restrict__ od) {
    int t = blockIdx.x * blockDim.x + threadIdx.x;
    int n = t >> 5, l = t & 31;
    if (n >= N_NODES) return;
    float4 hv = *(const float4*)(h + (size_t)n * HID + l * 4);
    int hh = l >> 2;
    float4 sa = *(const float4*)(av_s + hh * 16 + (l & 3) * 4);
    float4 da = *(const float4*)(av_d + hh * 16 + (l & 3) * 4);
    float ss = hv.x * sa.x + hv.y * sa.y + hv.z * sa.z + hv.w * sa.w;
    float sd = hv.x * da.x + hv.y * da.y + hv.z * da.z + hv.w * da.w;
    ss += __shfl_xor_sync(0xffffffffu, ss, 1);
    ss += __shfl_xor_sync(0xffffffffu, ss, 2);
    sd += __shfl_xor_sync(0xffffffffu, sd, 1);
    sd += __shfl_xor_sync(0xffffffffu, sd, 2);
    if ((l & 3) == 0) { os[n * 8 + hh] = ss; od[n * 8 + hh] = sd; }
}

// ---------------- layer0 aggregation: WARP per dst ----------------
__global__ void __launch_bounds__(256) agg0_kernel(
    const int* __restrict__ row_ptr, const int* __restrict__ csr_src,
    const float* __restrict__ as, const float* __restrict__ ad,
    const float* __restrict__ h, const float* __restrict__ b0,
    float* __restrict__ out) {
    __shared__ float s_al[8][32 * 8];
    __shared__ int s_src[8][32];
    int w = threadIdx.x >> 5, lane = threadIdx.x & 31;
    int dst = blockIdx.x * 8 + w;
    if (dst >= N_NODES) return;
    float4 d0 = ((const float4*)(ad + dst * 8))[0];
    float4 d1 = ((const float4*)(ad + dst * 8))[1];
    int s = row_ptr[dst], e = row_ptr[dst + 1];
    int hh = lane >> 2;
    float a0 = 0.f, a1 = 0.f, a2 = 0.f, a3 = 0.f, den = 0.f;
    for (int base = s; base < e; base += 32) {
        int n = min(32, e - base);
        if (lane < n) {
            int src = csr_src[base + lane];
            s_src[w][lane] = src;
            float4 s0 = ((const float4*)(as + src * 8))[0];
            float4 s1 = ((const float4*)(as + src * 8))[1];
            float v[8] = {s0.x + d0.x, s0.y + d0.y, s0.z + d0.z, s0.w + d0.w,
                          s1.x + d1.x, s1.y + d1.y, s1.z + d1.z, s1.w + d1.w};
#pragma unroll
            for (int j = 0; j < 8; j++) {
                float t = v[j];
                t = t > 0.f ? t : 0.2f * t;
                v[j] = __expf(t);
            }
            ((float4*)(s_al[w] + lane * 8))[0] = make_float4(v[0], v[1], v[2], v[3]);
            ((float4*)(s_al[w] + lane * 8))[1] = make_float4(v[4], v[5], v[6], v[7]);
        }
        __syncwarp();
#pragma unroll 4
        for (int i = 0; i < n; i++) {
            float a = s_al[w][i * 8 + hh];
            den += a;
            float4 hv = *(const float4*)(h + (size_t)s_src[w][i] * HID + lane * 4);
            a0 += a * hv.x; a1 += a * hv.y; a2 += a * hv.z; a3 += a * hv.w;
        }
        __syncwarp();
    }
    float r = 1.f / (den + 1e-16f);
    float4 bv = *(const float4*)(b0 + lane * 4);
    float o0 = a0 * r + bv.x, o1 = a1 * r + bv.y, o2 = a2 * r + bv.z, o3 = a3 * r + bv.w;
    o0 = o0 > 0.f ? o0 : expm1f(o0);
    o1 = o1 > 0.f ? o1 : expm1f(o1);
    o2 = o2 > 0.f ? o2 : expm1f(o2);
    o3 = o3 > 0.f ? o3 : expm1f(o3);
    *(float4*)(out + (size_t)dst * HID + lane * 4) = make_float4(o0, o1, o2, o3);
}

// ---------------- alpha layer1: block(128) per 8 nodes ----------------
__global__ void alpha1_kernel(const float* __restrict__ agg0,
                              const float* __restrict__ avs,
                              const float* __restrict__ avd,
                              float* __restrict__ os, float* __restrict__ od) {
    __shared__ float s_a[8][HID + 1];
    __shared__ float s_t[HID][16];
    int tid = threadIdx.x;
    int n0 = blockIdx.x * 8;
#pragma unroll
    for (int i = tid; i < HID * 8; i += 128) {
        int k = i >> 3, hh = i & 7;
        s_t[k][hh] = avs[i];
        s_t[k][8 + hh] = avd[i];
    }
#pragma unroll
    for (int r = 0; r < 8; r++) {
        int n = n0 + r;
        float v = (n < N_NODES) ? agg0[(size_t)n * HID + tid] : 0.f;
        s_a[r][tid] = v;
    }
    __syncthreads();
    int node = tid >> 4;
    int outp = tid & 15;
    float acc = 0.f;
#pragma unroll 8
    for (int k = 0; k < HID; k++) acc += s_a[node][k] * s_t[k][outp];
    int n = n0 + node;
    if (n < N_NODES) {
        if (outp < 8) os[n * 8 + outp] = acc;
        else od[n * 8 + (outp - 8)] = acc;
    }
}

// ---------------- layer1 aggregation: WARP per dst (z-trick), scalar acc + den-shuffle ----------------
__global__ void __launch_bounds__(256) aggz_kernel(
    const int* __restrict__ row_ptr, const int* __restrict__ csr_src,
    const float* __restrict__ as, const float* __restrict__ ad,
    const float* __restrict__ agg0,
    u16* __restrict__ zhi, u16* __restrict__ zlo) {
    __shared__ float s_al[8][32 * 8];
    __shared__ int s_src[8][32];
    int w = threadIdx.x >> 5, lane = threadIdx.x & 31;
    int dst = blockIdx.x * 8 + w;
    if (dst >= N_NODES) return;
    float4 d0 = ((const float4*)(ad + dst * 8))[0];
    float4 d1 = ((const float4*)(ad + dst * 8))[1];
    int s = row_ptr[dst], e = row_ptr[dst + 1];
    float acc[8][4];
#pragma unroll
    for (int hh = 0; hh < 8; hh++) {
#pragma unroll
        for (int j = 0; j < 4; j++) acc[hh][j] = 0.f;
    }
    float den_own = 0.f;          // this lane accumulates den for head (lane&7)
    int ownh = lane & 7;
    for (int base = s; base < e; base += 32) {
        int n = min(32, e - base);
        if (lane < n) {
            int src = csr_src[base + lane];
            s_src[w][lane] = src;
            float4 s0 = ((const float4*)(as + src * 8))[0];
            float4 s1 = ((const float4*)(as + src * 8))[1];
            float v[8] = {s0.x + d0.x, s0.y + d0.y, s0.z + d0.z, s0.w + d0.w,
                          s1.x + d1.x, s1.y + d1.y, s1.z + d1.z, s1.w + d1.w};
#pragma unroll
            for (int j = 0; j < 8; j++) {
                float t = v[j];
                t = t > 0.f ? t : 0.2f * t;
                v[j] = __expf(t);
            }
            ((float4*)(s_al[w] + lane * 8))[0] = make_float4(v[0], v[1], v[2], v[3]);
            ((float4*)(s_al[w] + lane * 8))[1] = make_float4(v[4], v[5], v[6], v[7]);
        }
        __syncwarp();
#pragma unroll 2
        for (int i = 0; i < n; i++) {
            float4 hv = *(const float4*)(agg0 + (size_t)s_src[w][i] * HID + lane * 4);
            den_own += s_al[w][i * 8 + ownh];
#pragma unroll
            for (int hh = 0; hh < 8; hh++) {
                float a = s_al[w][i * 8 + hh];
                acc[hh][0] += a * hv.x;
                acc[hh][1] += a * hv.y;
                acc[hh][2] += a * hv.z;
                acc[hh][3] += a * hv.w;
            }
        }
        __syncwarp();
    }
#pragma unroll
    for (int hh = 0; hh < 8; hh++) {
        float den = __shfl_sync(0xffffffffu, den_own, hh);  // lane hh holds head hh
        float r = 0.125f / (den + 1e-16f);
        u16 h0, l0, h1, l1, h2, l2, h3, l3;
        bsplit(acc[hh][0] * r, &h0, &l0);
        bsplit(acc[hh][1] * r, &h1, &l1);
        bsplit(acc[hh][2] * r, &h2, &l2);
        bsplit(acc[hh][3] * r, &h3, &l3);
        size_t o32 = ((size_t)dst * 1024 + hh * 128 + lane * 4) >> 1;
        ((uint2*)zhi)[o32 >> 1] = make_uint2((u32)h0 | ((u32)h1 << 16),
                                             (u32)h2 | ((u32)h3 << 16));
        ((uint2*)zlo)[o32 >> 1] = make_uint2((u32)l0 | ((u32)l1 << 16),
                                             (u32)l2 | ((u32)l3 << 16));
    }
}

// ---------------- finalize: log_softmax(z0+z1 + b1); warp per node ----------------
__global__ void finalize_kernel(const float* __restrict__ z0,
                                const float* __restrict__ z1,
                                const float* __restrict__ b1,
                                float* __restrict__ out) {
    int t = blockIdx.x * blockDim.x + threadIdx.x;
    int n = t >> 5, lane = t & 31;
    if (n >= N_NODES) return;
    float v0 = z0[(size_t)n * NCLS + lane] + z1[(size_t)n * NCLS + lane] + b1[lane];
    float v1 = z0[(size_t)n * NCLS + lane + 32] + z1[(size_t)n * NCLS + lane + 32] + b1[lane + 32];
    float mx = fmaxf(v0, v1);
#pragma unroll
    for (int o = 16; o; o >>= 1) mx = fmaxf(mx, __shfl_xor_sync(0xffffffffu, mx, o));
    float s = expf(v0 - mx) + expf(v1 - mx);
#pragma unroll
    for (int o = 16; o; o >>= 1) s += __shfl_xor_sync(0xffffffffu, s, o);
    float lse = mx + logf(s);
    out[(size_t)n * NCLS + lane] = v0 - lse;
    out[(size_t)n * NCLS + lane + 32] = v1 - lse;
}

// ---------------- launch ----------------
extern "C" void kernel_launch(void* const* d_in, const int* in_sizes, int n_in,
                              void* d_out, int out_size) {
    const float* x   = (const float*)d_in[0];
    const void*  ei  = d_in[1];
    const float* W0  = (const float*)d_in[2];
    const float* as0 = (const float*)d_in[3];
    const float* ad0 = (const float*)d_in[4];
    const float* b0  = (const float*)d_in[5];
    const float* W1  = (const float*)d_in[6];
    const float* as1 = (const float*)d_in[7];
    const float* ad1 = (const float*)d_in[8];
    const float* b1  = (const float*)d_in[9];
    float* out = (float*)d_out;

    float *h0, *as, *ad, *agg0, *avs, *avd, *zout, *zout2;
    u16 *w0thi, *w0tlo, *w1thi, *w1tlo, *zhi, *zlo;
    int *deg, *cur, *rowptr, *csrs, *bsum, *boff;
    cudaGetSymbolAddress((void**)&h0,    g_h0);
    cudaGetSymbolAddress((void**)&as,    g_as);
    cudaGetSymbolAddress((void**)&ad,    g_ad);
    cudaGetSymbolAddress((void**)&agg0,  g_agg0);
    cudaGetSymbolAddress((void**)&avs,   g_avs);
    cudaGetSymbolAddress((void**)&avd,   g_avd);
    cudaGetSymbolAddress((void**)&zout,  g_zout);
    cudaGetSymbolAddress((void**)&zout2, g_zout2);
    cudaGetSymbolAddress((void**)&w0thi, g_w0thi);
    cudaGetSymbolAddress((void**)&w0tlo, g_w0tlo);
    cudaGetSymbolAddress((void**)&w1thi, g_w1thi);
    cudaGetSymbolAddress((void**)&w1tlo, g_w1tlo);
    cudaGetSymbolAddress((void**)&zhi,   g_zhi);
    cudaGetSymbolAddress((void**)&zlo,   g_zlo);
    cudaGetSymbolAddress((void**)&deg,   g_deg);
    cudaGetSymbolAddress((void**)&cur,   g_cur);
    cudaGetSymbolAddress((void**)&rowptr,g_rowptr);
    cudaGetSymbolAddress((void**)&csrs,  g_csr_src);
    cudaGetSymbolAddress((void**)&bsum,  g_bsum);
    cudaGetSymbolAddress((void**)&boff,  g_boff);

    const int TB = 256;
    const int EBLK = (N_EDGES + TB - 1) / TB;
    const int NBLK = (N_NODES + TB - 1) / TB;
    const int WBLK = (N_NODES * 32 + TB - 1) / TB;
    const int MBLK = (N_NODES + 127) / 128;
    const int PREP_TOTAL = 256 * 128 + 128 * 512 + HID * HEADS;

    // launches 0-2
    init_kernel<<<NBLK, TB>>>(deg, cur, (const int*)ei);
    hist_kernel<<<EBLK, TB>>>(ei, deg);
    prep_all_kernel<<<(PREP_TOTAL + TB - 1) / TB, TB>>>(W0, W1, as1, ad1,
                                                        w0thi, w0tlo, w1thi, w1tlo, avs, avd);
    // launch 3: gemm0 (profiled)
    hgemmx_kernel<<<dim3(2, MBLK), 256>>>(N_NODES, 128, 256, x, w0thi, w0tlo, h0);

    // CSR completion
    scanA_kernel<<<SCAN_G, SCAN_B>>>(deg, bsum);
    scanB_kernel<<<1, 256>>>(bsum, boff);
    scanC_kernel<<<SCAN_G, SCAN_B>>>(deg, boff, rowptr);
    fill_kernel<<<EBLK, TB>>>(ei, rowptr, cur, csrs);

    // layer 0
    alpha0_kernel<<<WBLK, TB>>>(h0, as0, ad0, as, ad);
    agg0_kernel<<<(N_NODES + 7) / 8, 256>>>(rowptr, csrs, as, ad, h0, b0, agg0);

    // layer 1
    alpha1_kernel<<<(N_NODES + 7) / 8, 128>>>(agg0, avs, avd, as, ad);
    aggz_kernel<<<(N_NODES + 7) / 8, 256>>>(rowptr, csrs, as, ad, agg0, zhi, zlo);
    hgemm1_kernel<<<dim3(2, MBLK), 256>>>(N_NODES, zhi, zlo, w1thi, w1tlo, zout, zout2);
    finalize_kernel<<<WBLK, TB>>>(zout, zout2, b1, out);
}

// round 16
// speedup vs baseline: 1.1144x; 1.0317x over previous
#include <cuda_runtime.h>
#include <cuda_bf16.h>
#include <math.h>

#define N_NODES 50000
#define N_EDGES 600000
#define HEADS 8
#define HID 128
#define NCLS 64
#define SCAN_B 256
#define SCAN_G ((N_NODES + SCAN_B - 1) / SCAN_B)

typedef unsigned long long ull;
typedef unsigned short u16;
typedef unsigned int u32;

// ---------------- scratch ----------------
__device__ float g_h0[(size_t)N_NODES * HID];
__device__ float g_as[N_NODES * HEADS];
__device__ float g_ad[N_NODES * HEADS];
__device__ float g_agg0[(size_t)N_NODES * HID];
__device__ float g_avs[HID * HEADS];
__device__ float g_avd[HID * HEADS];
__device__ float g_zout[(size_t)N_NODES * NCLS];
__device__ float g_zout2[(size_t)N_NODES * NCLS];
__device__ u16 g_w0thi[128 * 256];
__device__ u16 g_w0tlo[128 * 256];
__device__ u16 g_w1thi[64 * 1024];
__device__ u16 g_w1tlo[64 * 1024];
__device__ u16 g_zhi[(size_t)N_NODES * 1024];
__device__ u16 g_zlo[(size_t)N_NODES * 1024];
__device__ int g_deg[N_NODES];
__device__ int g_cur[N_NODES];
__device__ int g_rowptr[N_NODES + 1];
__device__ int g_csr_src[N_EDGES];
__device__ int g_bsum[SCAN_G];
__device__ int g_boff[SCAN_G];
__device__ int g_is64;

// ================= warp MMA helpers =================
__device__ __forceinline__ u32 smem_u32(const void* p) {
    u32 a;
    asm("{ .reg .u64 t; cvta.to.shared.u64 t, %1; cvt.u32.u64 %0, t; }" : "=r"(a) : "l"(p));
    return a;
}
__device__ __forceinline__ void ldsm_x4(u32* r, u32 addr) {
    asm volatile("ldmatrix.sync.aligned.m8n8.x4.shared.b16 {%0,%1,%2,%3}, [%4];"
        : "=r"(r[0]), "=r"(r[1]), "=r"(r[2]), "=r"(r[3]) : "r"(addr));
}
__device__ __forceinline__ void mma_bf16(float* c, u32 a0, u32 a1, u32 a2, u32 a3,
                                         u32 b0, u32 b1) {
    asm volatile("mma.sync.aligned.m16n8k16.row.col.f32.bf16.bf16.f32 "
        "{%0,%1,%2,%3}, {%4,%5,%6,%7}, {%8,%9}, {%0,%1,%2,%3};"
        : "+f"(c[0]), "+f"(c[1]), "+f"(c[2]), "+f"(c[3])
        : "r"(a0), "r"(a1), "r"(a2), "r"(a3), "r"(b0), "r"(b1));
}

// ================= bf16 split =================
__device__ __forceinline__ void bsplit(float f, u16* hi, u16* lo) {
    __nv_bfloat16 h = __float2bfloat16(f);
    float r = f - __bfloat162float(h);
    __nv_bfloat16 l = __float2bfloat16(r);
    *hi = *(u16*)&h;
    *lo = *(u16*)&l;
}

// ---------------- init + dtype probe ----------------
__global__ void init_kernel(int* __restrict__ a, int* __restrict__ b,
                            const int* __restrict__ ei_raw) {
    int i = blockIdx.x * blockDim.x + threadIdx.x;
    if (i < N_NODES) { a[i] = 0; b[i] = 0; }
    if (i == 0) {
        int allz = 1;
#pragma unroll
        for (int j = 1; j < 64; j += 2)
            if (ei_raw[j] != 0) { allz = 0; break; }
        g_is64 = allz;
    }
}
__device__ __forceinline__ int edge_src(const void* ei, int e) {
    if (g_is64) return (int)((const long long*)ei)[e];
    return ((const int*)ei)[e];
}
__device__ __forceinline__ int edge_dst(const void* ei, int e) {
    if (g_is64) return (int)((const long long*)ei)[N_EDGES + e];
    return ((const int*)ei)[N_EDGES + e];
}

// ---------------- CSR build ----------------
__global__ void hist_kernel(const void* __restrict__ ei, int* __restrict__ deg) {
    int e = blockIdx.x * blockDim.x + threadIdx.x;
    if (e >= N_EDGES) return;
    atomicAdd(&deg[edge_dst(ei, e)], 1);
}
__global__ void scanA_kernel(const int* __restrict__ deg, int* __restrict__ bsum) {
    __shared__ int ws[8];
    int tid = threadIdx.x, lane = tid & 31, wid = tid >> 5;
    int i = blockIdx.x * SCAN_B + tid;
    int x = (i < N_NODES) ? deg[i] : 0;
#pragma unroll
    for (int o = 16; o; o >>= 1) x += __shfl_down_sync(0xffffffffu, x, o);
    if (lane == 0) ws[wid] = x;
    __syncthreads();
    if (tid == 0) {
        int t = 0;
#pragma unroll
        for (int j = 0; j < 8; j++) t += ws[j];
        bsum[blockIdx.x] = t;
    }
}
__global__ void scanB_kernel(const int* __restrict__ bsum, int* __restrict__ boff) {
    __shared__ int ws[8];
    int tid = threadIdx.x, lane = tid & 31, wid = tid >> 5;
    int v = (tid < SCAN_G) ? bsum[tid] : 0;
    int x = v;
#pragma unroll
    for (int o = 1; o < 32; o <<= 1) {
        int t = __shfl_up_sync(0xffffffffu, x, o);
        if (lane >= o) x += t;
    }
    if (lane == 31) ws[wid] = x;
    __syncthreads();
    if (tid == 0) {
        int run = 0;
#pragma unroll
        for (int j = 0; j < 8; j++) { int t = ws[j]; ws[j] = run; run += t; }
    }
    __syncthreads();
    if (tid < SCAN_G) boff[tid] = x - v + ws[wid];
}
__global__ void scanC_kernel(const int* __restrict__ deg, const int* __restrict__ boff,
                             int* __restrict__ row_ptr) {
    __shared__ int ws[8];
    int tid = threadIdx.x, lane = tid & 31, wid = tid >> 5;
    int i = blockIdx.x * SCAN_B + tid;
    int v = (i < N_NODES) ? deg[i] : 0;
    int x = v;
#pragma unroll
    for (int o = 1; o < 32; o <<= 1) {
        int t = __shfl_up_sync(0xffffffffu, x, o);
        if (lane >= o) x += t;
    }
    if (lane == 31) ws[wid] = x;
    __syncthreads();
    if (tid == 0) {
        int run = 0;
#pragma unroll
        for (int j = 0; j < 8; j++) { int t = ws[j]; ws[j] = run; run += t; }
    }
    __syncthreads();
    if (i < N_NODES) row_ptr[i] = x - v + ws[wid] + boff[blockIdx.x];
    if (blockIdx.x == 0 && tid == 0) row_ptr[N_NODES] = N_EDGES;
}
__global__ void fill_kernel(const void* __restrict__ ei, const int* __restrict__ row_ptr,
                            int* __restrict__ cur, int* __restrict__ csr_src) {
    int e = blockIdx.x * blockDim.x + threadIdx.x;
    if (e >= N_EDGES) return;
    int dst = edge_dst(ei, e);
    int src = edge_src(ei, e);
    int p = row_ptr[dst] + atomicAdd(&cur[dst], 1);
    csr_src[p] = src;
}

// ---------------- prep_all: W0 transpose+split | W1 stack+split | W1·a fold ----------------
__global__ void prep_all_kernel(const float* __restrict__ W0, const float* __restrict__ W1,
                                const float* __restrict__ a_s, const float* __restrict__ a_d,
                                u16* __restrict__ w0thi, u16* __restrict__ w0tlo,
                                u16* __restrict__ w1thi, u16* __restrict__ w1tlo,
                                float* __restrict__ avs, float* __restrict__ avd) {
    int i = blockIdx.x * blockDim.x + threadIdx.x;
    if (i < 256 * 128) {
        int k = i >> 7, n = i & 127;
        bsplit(W0[i], &w0thi[n * 256 + k], &w0tlo[n * 256 + k]);
    } else if (i < 256 * 128 + 128 * 512) {
        int j = i - 256 * 128;
        int k = j >> 9;
        int jj = j & 511;
        int hh = jj >> 6, c = jj & 63;
        int o = c * 1024 + hh * 128 + k;
        bsplit(W1[j], &w1thi[o], &w1tlo[o]);
    } else {
        int o = i - 256 * 128 - 128 * 512;
        if (o < HID * HEADS) {
            int k = o >> 3, hh = o & 7;
            const float* wrow = W1 + (size_t)k * 512 + hh * 64;
            const float* sv = a_s + hh * 64;
            const float* dv = a_d + hh * 64;
            float ss = 0.f, sd = 0.f;
#pragma unroll 16
            for (int c = 0; c < 64; c++) {
                float w = wrow[c];
                ss += w * sv[c];
                sd += w * dv[c];
            }
            avs[k * 8 + hh] = ss;
            avd[k * 8 + hh] = sd;
        }
    }
}

// ================= gemm0: fp32 A in-staging split, C[M,128]=A[M,256]@B^T =================
__global__ void __launch_bounds__(256) hgemmx_kernel(
    int M, int N, int K,
    const float* __restrict__ A,
    const u16* __restrict__ Bhi, const u16* __restrict__ Blo,
    float* __restrict__ C) {
    __shared__ u16 Ash[2][128][40];
    __shared__ u16 Bsh[2][64][40];
    int tid = threadIdx.x, lane = tid & 31, wid = tid >> 5;
    int row0 = blockIdx.y * 128;
    int col0 = blockIdx.x * 64;
    int wm = wid & 3;
    int wn = wid >> 2;

    float acc[8][4];
#pragma unroll
    for (int i = 0; i < 8; i++)
#pragma unroll
        for (int j = 0; j < 4; j++) acc[i][j] = 0.f;

    const int arow = wm * 32 + (lane & 15);
    const int aoff = (lane >> 4) << 3;
    const int bn = wn * 32 + (lane & 7) + ((lane >> 4) << 3);
    const int boff = ((lane >> 3) & 1) << 3;

    float4 pfa[2][2];
    uint4 pbh, pbl;

    auto ldg = [&](int k0) {
#pragma unroll
        for (int i = 0; i < 2; i++) {
            int idx = tid + i * 256;
            int r = idx >> 2, q = idx & 3;
            int g = row0 + r;
            if (g < M) {
                const float* base = A + (size_t)g * K + k0 + q * 8;
                pfa[i][0] = *(const float4*)base;
                pfa[i][1] = *(const float4*)(base + 4);
            } else {
                pfa[i][0] = make_float4(0.f, 0.f, 0.f, 0.f);
                pfa[i][1] = make_float4(0.f, 0.f, 0.f, 0.f);
            }
        }
        int r = tid >> 2, q = tid & 3;
        pbh = *(const uint4*)(Bhi + (size_t)(col0 + r) * K + k0 + q * 8);
        pbl = *(const uint4*)(Blo + (size_t)(col0 + r) * K + k0 + q * 8);
    };
    auto sts = [&]() {
#pragma unroll
        for (int i = 0; i < 2; i++) {
            int idx = tid + i * 256;
            int r = idx >> 2, q = idx & 3;
            float f[8] = {pfa[i][0].x, pfa[i][0].y, pfa[i][0].z, pfa[i][0].w,
                          pfa[i][1].x, pfa[i][1].y, pfa[i][1].z, pfa[i][1].w};
            u32 hw[4], lw[4];
#pragma unroll
            for (int j = 0; j < 4; j++) {
                u16 h0, l0, h1, l1;
                bsplit(f[2 * j], &h0, &l0);
                bsplit(f[2 * j + 1], &h1, &l1);
                hw[j] = (u32)h0 | ((u32)h1 << 16);
                lw[j] = (u32)l0 | ((u32)l1 << 16);
            }
            *(uint4*)&Ash[0][r][q * 8] = make_uint4(hw[0], hw[1], hw[2], hw[3]);
            *(uint4*)&Ash[1][r][q * 8] = make_uint4(lw[0], lw[1], lw[2], lw[3]);
        }
        int r = tid >> 2, q = tid & 3;
        *(uint4*)&Bsh[0][r][q * 8] = pbh;
        *(uint4*)&Bsh[1][r][q * 8] = pbl;
    };

    ldg(0); sts(); __syncthreads();
    for (int k0 = 0; k0 < K; k0 += 32) {
        if (k0 + 32 < K) ldg(k0 + 32);
#pragma unroll
        for (int ks = 0; ks < 2; ks++) {
            u32 ah[2][4], al[2][4], bh[2][4], bl[2][4];
            int akk = ks * 16 + aoff;
            int bkk = ks * 16 + boff;
#pragma unroll
            for (int mi = 0; mi < 2; mi++) {
                ldsm_x4(ah[mi], smem_u32(&Ash[0][arow + mi * 16][akk]));
                ldsm_x4(al[mi], smem_u32(&Ash[1][arow + mi * 16][akk]));
            }
#pragma unroll
            for (int ni2 = 0; ni2 < 2; ni2++) {
                ldsm_x4(bh[ni2], smem_u32(&Bsh[0][bn + ni2 * 16][bkk]));
                ldsm_x4(bl[ni2], smem_u32(&Bsh[1][bn + ni2 * 16][bkk]));
            }
#pragma unroll
            for (int mi = 0; mi < 2; mi++) {
#pragma unroll
                for (int ni = 0; ni < 4; ni++) {
                    float* c = acc[mi * 4 + ni];
                    u32 b0h = bh[ni >> 1][(ni & 1) * 2];
                    u32 b1h = bh[ni >> 1][(ni & 1) * 2 + 1];
                    u32 b0l = bl[ni >> 1][(ni & 1) * 2];
                    u32 b1l = bl[ni >> 1][(ni & 1) * 2 + 1];
                    mma_bf16(c, ah[mi][0], ah[mi][1], ah[mi][2], ah[mi][3], b0h, b1h);
                    mma_bf16(c, ah[mi][0], ah[mi][1], ah[mi][2], ah[mi][3], b0l, b1l);
                    mma_bf16(c, al[mi][0], al[mi][1], al[mi][2], al[mi][3], b0h, b1h);
                }
            }
        }
        if (k0 + 32 < K) { __syncthreads(); sts(); __syncthreads(); }
    }

    int gid = lane >> 2, tig = lane & 3;
#pragma unroll
    for (int mi = 0; mi < 2; mi++) {
#pragma unroll
        for (int ni = 0; ni < 4; ni++) {
            float* c = acc[mi * 4 + ni];
            int r = row0 + wm * 32 + mi * 16 + gid;
            int col = col0 + wn * 32 + ni * 8 + tig * 2;
            if (r < M) *(float2*)(C + (size_t)r * N + col) = make_float2(c[0], c[1]);
            if (r + 8 < M) *(float2*)(C + (size_t)(r + 8) * N + col) = make_float2(c[2], c[3]);
        }
    }
}

// ================= gemm1 split-K: two K=512 slices =================
__global__ void __launch_bounds__(256) hgemm1_kernel(
    int M,
    const u16* __restrict__ Ahi, const u16* __restrict__ Alo,
    const u16* __restrict__ Bhi, const u16* __restrict__ Blo,
    float* __restrict__ C0, float* __restrict__ C1) {
    const int LDA = 1024, KS = 512, N = 64;
    __shared__ u16 Ash[2][128][40];
    __shared__ u16 Bsh[2][64][40];
    int tid = threadIdx.x, lane = tid & 31, wid = tid >> 5;
    int row0 = blockIdx.y * 128;
    int kbeg = blockIdx.x * KS;
    float* C = blockIdx.x ? C1 : C0;
    int wm = wid & 3;
    int wn = wid >> 2;

    float acc[8][4];
#pragma unroll
    for (int i = 0; i < 8; i++)
#pragma unroll
        for (int j = 0; j < 4; j++) acc[i][j] = 0.f;

    const int arow = wm * 32 + (lane & 15);
    const int aoff = (lane >> 4) << 3;
    const int bn = wn * 32 + (lane & 7) + ((lane >> 4) << 3);
    const int boff = ((lane >> 3) & 1) << 3;

    uint4 pah[2], pal[2], pbh, pbl;

    auto ldg = [&](int k0) {
#pragma unroll
        for (int i = 0; i < 2; i++) {
            int idx = tid + i * 256;
            int r = idx >> 2, q = idx & 3;
            int g = row0 + r;
            if (g < M) {
                pah[i] = *(const uint4*)(Ahi + (size_t)g * LDA + kbeg + k0 + q * 8);
                pal[i] = *(const uint4*)(Alo + (size_t)g * LDA + kbeg + k0 + q * 8);
            } else {
                pah[i] = make_uint4(0, 0, 0, 0);
                pal[i] = make_uint4(0, 0, 0, 0);
            }
        }
        int r = tid >> 2, q = tid & 3;
        pbh = *(const uint4*)(Bhi + (size_t)r * LDA + kbeg + k0 + q * 8);
        pbl = *(const uint4*)(Blo + (size_t)r * LDA + kbeg + k0 + q * 8);
    };
    auto sts = [&]() {
#pragma unroll
        for (int i = 0; i < 2; i++) {
            int idx = tid + i * 256;
            int r = idx >> 2, q = idx & 3;
            *(uint4*)&Ash[0][r][q * 8] = pah[i];
            *(uint4*)&Ash[1][r][q * 8] = pal[i];
        }
        int r = tid >> 2, q = tid & 3;
        *(uint4*)&Bsh[0][r][q * 8] = pbh;
        *(uint4*)&Bsh[1][r][q * 8] = pbl;
    };

    ldg(0); sts(); __syncthreads();
    for (int k0 = 0; k0 < KS; k0 += 32) {
        if (k0 + 32 < KS) ldg(k0 + 32);
#pragma unroll
        for (int ks = 0; ks < 2; ks++) {
            u32 ah[2][4], al[2][4], bh[2][4], bl[2][4];
            int akk = ks * 16 + aoff;
            int bkk = ks * 16 + boff;
#pragma unroll
            for (int mi = 0; mi < 2; mi++) {
                ldsm_x4(ah[mi], smem_u32(&Ash[0][arow + mi * 16][akk]));
                ldsm_x4(al[mi], smem_u32(&Ash[1][arow + mi * 16][akk]));
            }
#pragma unroll
            for (int ni2 = 0; ni2 < 2; ni2++) {
                ldsm_x4(bh[ni2], smem_u32(&Bsh[0][bn + ni2 * 16][bkk]));
                ldsm_x4(bl[ni2], smem_u32(&Bsh[1][bn + ni2 * 16][bkk]));
            }
#pragma unroll
            for (int mi = 0; mi < 2; mi++) {
#pragma unroll
                for (int ni = 0; ni < 4; ni++) {
                    float* c = acc[mi * 4 + ni];
                    u32 b0h = bh[ni >> 1][(ni & 1) * 2];
                    u32 b1h = bh[ni >> 1][(ni & 1) * 2 + 1];
                    u32 b0l = bl[ni >> 1][(ni & 1) * 2];
                    u32 b1l = bl[ni >> 1][(ni & 1) * 2 + 1];
                    mma_bf16(c, ah[mi][0], ah[mi][1], ah[mi][2], ah[mi][3], b0h, b1h);
                    mma_bf16(c, ah[mi][0], ah[mi][1], ah[mi][2], ah[mi][3], b0l, b1l);
                    mma_bf16(c, al[mi][0], al[mi][1], al[mi][2], al[mi][3], b0h, b1h);
                }
            }
        }
        if (k0 + 32 < KS) { __syncthreads(); sts(); __syncthreads(); }
    }

    int gid = lane >> 2, tig = lane & 3;
#pragma unroll
    for (int mi = 0; mi < 2; mi++) {
#pragma unroll
        for (int ni = 0; ni < 4; ni++) {
            float* c = acc[mi * 4 + ni];
            int r = row0 + wm * 32 + mi * 16 + gid;
            int col = wn * 32 + ni * 8 + tig * 2;
            if (r < M) *(float2*)(C + (size_t)r * N + col) = make_float2(c[0], c[1]);
            if (r + 8 < M) *(float2*)(C + (size_t)(r + 8) * N + col) = make_float2(c[2], c[3]);
        }
    }
}

// ---------------- alpha layer0: warp per node ----------------
__global__ void alpha0_kernel(const float* __restrict__ h,
                              const float* __restrict__ av_s,
                              const float* __restrict__ av_d,
                              float* __restrict__ os, float* __restrict__ od) {
    int t = blockIdx.x * blockDim.x + threadIdx.x;
    int n = t >> 5, l = t & 31;
    if (n >= N_NODES) return;
    float4 hv = *(const float4*)(h + (size_t)n * HID + l * 4);
    int hh = l >> 2;
    float4 sa = *(const float4*)(av_s + hh * 16 + (l & 3) * 4);
    float4 da = *(const float4*)(av_d + hh * 16 + (l & 3) * 4);
    float ss = hv.x * sa.x + hv.y * sa.y + hv.z * sa.z + hv.w * sa.w;
    float sd = hv.x * da.x + hv.y * da.y + hv.z * da.z + hv.w * da.w;
    ss += __shfl_xor_sync(0xffffffffu, ss, 1);
    ss += __shfl_xor_sync(0xffffffffu, ss, 2);
    sd += __shfl_xor_sync(0xffffffffu, sd, 1);
    sd += __shfl_xor_sync(0xffffffffu, sd, 2);
    if ((l & 3) == 0) { os[n * 8 + hh] = ss; od[n * 8 + hh] = sd; }
}

// ---------------- layer0 aggregation: WARP per dst ----------------
__global__ void __launch_bounds__(256) agg0_kernel(
    const int* __restrict__ row_ptr, const int* __restrict__ csr_src,
    const float* __restrict__ as, const float* __restrict__ ad,
    const float* __restrict__ h, const float* __restrict__ b0,
    float* __restrict__ out) {
    __shared__ float s_al[8][32 * 8];
    __shared__ int s_src[8][32];
    int w = threadIdx.x >> 5, lane = threadIdx.x & 31;
    int dst = blockIdx.x * 8 + w;
    if (dst >= N_NODES) return;
    float4 d0 = ((const float4*)(ad + dst * 8))[0];
    float4 d1 = ((const float4*)(ad + dst * 8))[1];
    int s = row_ptr[dst], e = row_ptr[dst + 1];
    int hh = lane >> 2;
    float a0 = 0.f, a1 = 0.f, a2 = 0.f, a3 = 0.f, den = 0.f;
    for (int base = s; base < e; base += 32) {
        int n = min(32, e - base);
        if (lane < n) {
            int src = csr_src[base + lane];
            s_src[w][lane] = src;
            float4 s0 = ((const float4*)(as + src * 8))[0];
            float4 s1 = ((const float4*)(as + src * 8))[1];
            float v[8] = {s0.x + d0.x, s0.y + d0.y, s0.z + d0.z, s0.w + d0.w,
                          s1.x + d1.x, s1.y + d1.y, s1.z + d1.z, s1.w + d1.w};
#pragma unroll
            for (int j = 0; j < 8; j++) {
                float t = v[j];
                t = t > 0.f ? t : 0.2f * t;
                v[j] = __expf(t);
            }
            ((float4*)(s_al[w] + lane * 8))[0] = make_float4(v[0], v[1], v[2], v[3]);
            ((float4*)(s_al[w] + lane * 8))[1] = make_float4(v[4], v[5], v[6], v[7]);
        }
        __syncwarp();
#pragma unroll 4
        for (int i = 0; i < n; i++) {
            float a = s_al[w][i * 8 + hh];
            den += a;
            float4 hv = *(const float4*)(h + (size_t)s_src[w][i] * HID + lane * 4);
            a0 += a * hv.x; a1 += a * hv.y; a2 += a * hv.z; a3 += a * hv.w;
        }
        __syncwarp();
    }
    float r = 1.f / (den + 1e-16f);
    float4 bv = *(const float4*)(b0 + lane * 4);
    float o0 = a0 * r + bv.x, o1 = a1 * r + bv.y, o2 = a2 * r + bv.z, o3 = a3 * r + bv.w;
    o0 = o0 > 0.f ? o0 : expm1f(o0);
    o1 = o1 > 0.f ? o1 : expm1f(o1);
    o2 = o2 > 0.f ? o2 : expm1f(o2);
    o3 = o3 > 0.f ? o3 : expm1f(o3);
    *(float4*)(out + (size_t)dst * HID + lane * 4) = make_float4(o0, o1, o2, o3);
}

// ---------------- alpha layer1: block(128) per 8 nodes ----------------
__global__ void alpha1_kernel(const float* __restrict__ agg0,
                              const float* __restrict__ avs,
                              const float* __restrict__ avd,
                              float* __restrict__ os, float* __restrict__ od) {
    __shared__ float s_a[8][HID + 1];
    __shared__ float s_t[HID][16];
    int tid = threadIdx.x;
    int n0 = blockIdx.x * 8;
#pragma unroll
    for (int i = tid; i < HID * 8; i += 128) {
        int k = i >> 3, hh = i & 7;
        s_t[k][hh] = avs[i];
        s_t[k][8 + hh] = avd[i];
    }
#pragma unroll
    for (int r = 0; r < 8; r++) {
        int n = n0 + r;
        float v = (n < N_NODES) ? agg0[(size_t)n * HID + tid] : 0.f;
        s_a[r][tid] = v;
    }
    __syncthreads();
    int node = tid >> 4;
    int outp = tid & 15;
    float acc = 0.f;
#pragma unroll 8
    for (int k = 0; k < HID; k++) acc += s_a[node][k] * s_t[k][outp];
    int n = n0 + node;
    if (n < N_NODES) {
        if (outp < 8) os[n * 8 + outp] = acc;
        else od[n * 8 + (outp - 8)] = acc;
    }
}

// ---------------- layer1 aggregation: WARP per dst, den-shuffle ----------------
__global__ void __launch_bounds__(256) aggz_kernel(
    const int* __restrict__ row_ptr, const int* __restrict__ csr_src,
    const float* __restrict__ as, const float* __restrict__ ad,
    const float* __restrict__ agg0,
    u16* __restrict__ zhi, u16* __restrict__ zlo) {
    __shared__ float s_al[8][32 * 8];
    __shared__ int s_src[8][32];
    int w = threadIdx.x >> 5, lane = threadIdx.x & 31;
    int dst = blockIdx.x * 8 + w;
    if (dst >= N_NODES) return;
    float4 d0 = ((const float4*)(ad + dst * 8))[0];
    float4 d1 = ((const float4*)(ad + dst * 8))[1];
    int s = row_ptr[dst], e = row_ptr[dst + 1];
    float acc[8][4];
#pragma unroll
    for (int hh = 0; hh < 8; hh++) {
#pragma unroll
        for (int j = 0; j < 4; j++) acc[hh][j] = 0.f;
    }
    float den_own = 0.f;
    int ownh = lane & 7;
    for (int base = s; base < e; base += 32) {
        int n = min(32, e - base);
        if (lane < n) {
            int src = csr_src[base + lane];
            s_src[w][lane] = src;
            float4 s0 = ((const float4*)(as + src * 8))[0];
            float4 s1 = ((const float4*)(as + src * 8))[1];
            float v[8] = {s0.x + d0.x, s0.y + d0.y, s0.z + d0.z, s0.w + d0.w,
                          s1.x + d1.x, s1.y + d1.y, s1.z + d1.z, s1.w + d1.w};
#pragma unroll
            for (int j = 0; j < 8; j++) {
                float t = v[j];
                t = t > 0.f ? t : 0.2f * t;
                v[j] = __expf(t);
            }
            ((float4*)(s_al[w] + lane * 8))[0] = make_float4(v[0], v[1], v[2], v[3]);
            ((float4*)(s_al[w] + lane * 8))[1] = make_float4(v[4], v[5], v[6], v[7]);
        }
        __syncwarp();
#pragma unroll 2
        for (int i = 0; i < n; i++) {
            float4 hv = *(const float4*)(agg0 + (size_t)s_src[w][i] * HID + lane * 4);
            den_own += s_al[w][i * 8 + ownh];
#pragma unroll
            for (int hh = 0; hh < 8; hh++) {
                float a = s_al[w][i * 8 + hh];
                acc[hh][0] += a * hv.x;
                acc[hh][1] += a * hv.y;
                acc[hh][2] += a * hv.z;
                acc[hh][3] += a * hv.w;
            }
        }
        __syncwarp();
    }
#pragma unroll
    for (int hh = 0; hh < 8; hh++) {
        float den = __shfl_sync(0xffffffffu, den_own, hh);
        float r = 0.125f / (den + 1e-16f);
        u16 h0, l0, h1, l1, h2, l2, h3, l3;
        bsplit(acc[hh][0] * r, &h0, &l0);
        bsplit(acc[hh][1] * r, &h1, &l1);
        bsplit(acc[hh][2] * r, &h2, &l2);
        bsplit(acc[hh][3] * r, &h3, &l3);
        size_t o32 = ((size_t)dst * 1024 + hh * 128 + lane * 4) >> 1;
        ((uint2*)zhi)[o32 >> 1] = make_uint2((u32)h0 | ((u32)h1 << 16),
                                             (u32)h2 | ((u32)h3 << 16));
        ((uint2*)zlo)[o32 >> 1] = make_uint2((u32)l0 | ((u32)l1 << 16),
                                             (u32)l2 | ((u32)l3 << 16));
    }
}

// ---------------- finalize: log_softmax(z0+z1 + b1); warp per node ----------------
__global__ void finalize_kernel(const float* __restrict__ z0,
                                const float* __restrict__ z1,
                                const float* __restrict__ b1,
                                float* __restrict__ out) {
    int t = blockIdx.x * blockDim.x + threadIdx.x;
    int n = t >> 5, lane = t & 31;
    if (n >= N_NODES) return;
    float v0 = z0[(size_t)n * NCLS + lane] + z1[(size_t)n * NCLS + lane] + b1[lane];
    float v1 = z0[(size_t)n * NCLS + lane + 32] + z1[(size_t)n * NCLS + lane + 32] + b1[lane + 32];
    float mx = fmaxf(v0, v1);
#pragma unroll
    for (int o = 16; o; o >>= 1) mx = fmaxf(mx, __shfl_xor_sync(0xffffffffu, mx, o));
    float s = expf(v0 - mx) + expf(v1 - mx);
#pragma unroll
    for (int o = 16; o; o >>= 1) s += __shfl_xor_sync(0xffffffffu, s, o);
    float lse = mx + logf(s);
    out[(size_t)n * NCLS + lane] = v0 - lse;
    out[(size_t)n * NCLS + lane + 32] = v1 - lse;
}

// ---------------- launch (stream fork/join for CSR || GEMM overlap) ----------------
extern "C" void kernel_launch(void* const* d_in, const int* in_sizes, int n_in,
                              void* d_out, int out_size) {
    const float* x   = (const float*)d_in[0];
    const void*  ei  = d_in[1];
    const float* W0  = (const float*)d_in[2];
    const float* as0 = (const float*)d_in[3];
    const float* ad0 = (const float*)d_in[4];
    const float* b0  = (const float*)d_in[5];
    const float* W1  = (const float*)d_in[6];
    const float* as1 = (const float*)d_in[7];
    const float* ad1 = (const float*)d_in[8];
    const float* b1  = (const float*)d_in[9];
    float* out = (float*)d_out;

    float *h0, *as, *ad, *agg0, *avs, *avd, *zout, *zout2;
    u16 *w0thi, *w0tlo, *w1thi, *w1tlo, *zhi, *zlo;
    int *deg, *cur, *rowptr, *csrs, *bsum, *boff;
    cudaGetSymbolAddress((void**)&h0,    g_h0);
    cudaGetSymbolAddress((void**)&as,    g_as);
    cudaGetSymbolAddress((void**)&ad,    g_ad);
    cudaGetSymbolAddress((void**)&agg0,  g_agg0);
    cudaGetSymbolAddress((void**)&avs,   g_avs);
    cudaGetSymbolAddress((void**)&avd,   g_avd);
    cudaGetSymbolAddress((void**)&zout,  g_zout);
    cudaGetSymbolAddress((void**)&zout2, g_zout2);
    cudaGetSymbolAddress((void**)&w0thi, g_w0thi);
    cudaGetSymbolAddress((void**)&w0tlo, g_w0tlo);
    cudaGetSymbolAddress((void**)&w1thi, g_w1thi);
    cudaGetSymbolAddress((void**)&w1tlo, g_w1tlo);
    cudaGetSymbolAddress((void**)&zhi,   g_zhi);
    cudaGetSymbolAddress((void**)&zlo,   g_zlo);
    cudaGetSymbolAddress((void**)&deg,   g_deg);
    cudaGetSymbolAddress((void**)&cur,   g_cur);
    cudaGetSymbolAddress((void**)&rowptr,g_rowptr);
    cudaGetSymbolAddress((void**)&csrs,  g_csr_src);
    cudaGetSymbolAddress((void**)&bsum,  g_bsum);
    cudaGetSymbolAddress((void**)&boff,  g_boff);

    const int TB = 256;
    const int EBLK = (N_EDGES + TB - 1) / TB;
    const int NBLK = (N_NODES + TB - 1) / TB;
    const int WBLK = (N_NODES * 32 + TB - 1) / TB;
    const int MBLK = (N_NODES + 127) / 128;
    const int PREP_TOTAL = 256 * 128 + 128 * 512 + HID * HEADS;

    // Side stream for the weight-prep / gemm0 / alpha0 chain (independent of CSR build).
    // Created per call; intentionally NOT destroyed here (destroying a stream whose ops
    // were just captured is illegal mid-capture; kernel_launch runs only a handful of times).
    cudaStream_t s2;
    cudaStreamCreateWithFlags(&s2, cudaStreamNonBlocking);
    cudaEvent_t evF, evJ;
    cudaEventCreateWithFlags(&evF, cudaEventDisableTiming);
    cudaEventCreateWithFlags(&evJ, cudaEventDisableTiming);

    // main stream: CSR chain
    init_kernel<<<NBLK, TB>>>(deg, cur, (const int*)ei);
    cudaEventRecord(evF, 0);
    cudaStreamWaitEvent(s2, evF, 0);

    hist_kernel<<<EBLK, TB>>>(ei, deg);                     // launch 1 (main)
    prep_all_kernel<<<(PREP_TOTAL + TB - 1) / TB, TB, 0, s2>>>(
        W0, W1, as1, ad1, w0thi, w0tlo, w1thi, w1tlo, avs, avd);  // launch 2 (s2)
    hgemmx_kernel<<<dim3(2, MBLK), 256, 0, s2>>>(N_NODES, 128, 256, x, w0thi, w0tlo, h0);  // launch 3 (s2, profiled)
    scanA_kernel<<<SCAN_G, SCAN_B>>>(deg, bsum);
    scanB_kernel<<<1, 256>>>(bsum, boff);
    scanC_kernel<<<SCAN_G, SCAN_B>>>(deg, boff, rowptr);
    fill_kernel<<<EBLK, TB>>>(ei, rowptr, cur, csrs);
    alpha0_kernel<<<WBLK, TB, 0, s2>>>(h0, as0, ad0, as, ad);

    cudaEventRecord(evJ, s2);
    cudaStreamWaitEvent(0, evJ, 0);

    // joined: layer-0 aggregation onward (main stream)
    agg0_kernel<<<(N_NODES + 7) / 8, 256>>>(rowptr, csrs, as, ad, h0, b0, agg0);
    alpha1_kernel<<<(N_NODES + 7) / 8, 128>>>(agg0, avs, avd, as, ad);
    aggz_kernel<<<(N_NODES + 7) / 8, 256>>>(rowptr, csrs, as, ad, agg0, zhi, zlo);
    hgemm1_kernel<<<dim3(2, MBLK), 256>>>(N_NODES, zhi, zlo, w1thi, w1tlo, zout, zout2);
    finalize_kernel<<<WBLK, TB>>>(zout, zout2, b1, out);
}